// round 2
// baseline (speedup 1.0000x reference)
#include <cuda_runtime.h>

#define NN  100000
#define EE  1600000
#define INF 256
#define HH  64
#define CC  16

// ---------------- scratch (no allocations allowed -> device globals) ----------------
__device__ float g_bufA[(size_t)NN * HH];   // 25.6 MB
__device__ float g_bufB[(size_t)NN * HH];   // 25.6 MB
__device__ float g_deg[NN];
__device__ float g_dinv[NN];
__device__ int   g_cnt[NN];
__device__ int   g_rowptr[NN + 1];
__device__ int   g_cursor[NN];
__device__ int   g_col[EE];                 // 6.4 MB
__device__ float g_val[EE];                 // 6.4 MB
__device__ int   g_idx64;

// edge_index may be int64 (reference declares it) or int32 (jax x64-disabled
// canonicalization). Detected at runtime by k_detect; branch on device flag.
__device__ __forceinline__ int ld_idx(const void* ei, long long pos) {
    if (g_idx64)
        return (int)((const long long*)ei)[pos];
    return ((const int*)ei)[pos];
}

// Odd 32-bit words of the first 64 index entries: all zero iff int64
// (values are in [0, 100000), so high words are 0; for int32 these words are
// random indices, P(all 64 == 0) ~ 1e-320).
__global__ void k_detect(const unsigned int* ei) {
    if (threadIdx.x == 0) {
        unsigned v = 0;
        for (int i = 0; i < 64; i++) v |= ei[2 * i + 1];
        g_idx64 = (v == 0) ? 1 : 0;
    }
}

__global__ void k_init() {
    int i = blockIdx.x * blockDim.x + threadIdx.x;
    if (i < NN) { g_deg[i] = 1.0f; g_cnt[i] = 0; }   // self-loop weight 1
}

__global__ void k_degcnt(const void* ei, const float* __restrict__ ew) {
    int e = blockIdx.x * blockDim.x + threadIdx.x;
    if (e < EE) {
        int d = ld_idx(ei, (long long)EE + e);       // dst row
        atomicAdd(&g_deg[d], ew[e]);
        atomicAdd(&g_cnt[d], 1);
    }
}

__global__ void k_dinv() {
    int i = blockIdx.x * blockDim.x + threadIdx.x;
    if (i < NN) g_dinv[i] = rsqrtf(g_deg[i]);        // deg >= 1 always
}

// Single-block exclusive scan of g_cnt -> g_rowptr / g_cursor.
__global__ void k_scan() {
    __shared__ int sm[1024];
    const int t  = threadIdx.x;
    const int CH = (NN + 1023) / 1024;               // 98
    int start = t * CH;
    int end   = start + CH; if (end > NN) end = NN;
    if (start > NN) start = NN;

    int s = 0;
    for (int i = start; i < end; i++) s += g_cnt[i];
    sm[t] = s;
    __syncthreads();
    for (int off = 1; off < 1024; off <<= 1) {
        int v = (t >= off) ? sm[t - off] : 0;
        __syncthreads();
        sm[t] += v;
        __syncthreads();
    }
    int run = sm[t] - s;                             // exclusive base
    for (int i = start; i < end; i++) {
        g_rowptr[i] = run;
        g_cursor[i] = run;
        run += g_cnt[i];
    }
    if (t == 0) g_rowptr[NN] = EE;
}

__global__ void k_scatter(const void* ei, const float* __restrict__ ew) {
    int e = blockIdx.x * blockDim.x + threadIdx.x;
    if (e < EE) {
        int s = ld_idx(ei, e);
        int d = ld_idx(ei, (long long)EE + e);
        int pos = atomicAdd(&g_cursor[d], 1);
        g_col[pos] = s;
        g_val[pos] = g_dinv[s] * ew[e] * g_dinv[d];
    }
}

// ---------------- GEMM: [nrows, KTOT] @ [KTOT, 64] -> [nrows, 64] ----------------
// block 128 threads = 8 feat-groups x 16 row-groups; each thread 4 rows x 8 feats.
template <int KTOT, bool BIAS_RELU>
__global__ void __launch_bounds__(128)
gemm64(const float* __restrict__ A, const float* __restrict__ W,
       const float* __restrict__ bias, float* __restrict__ out, int nrows) {
    __shared__ float xs[64][65];                     // [k][row], pad -> conflict-free
    __shared__ __align__(16) float ws[64][64];       // [k][feat]
    const int tid = threadIdx.x;
    const int tx  = tid & 7;                         // feat group -> f0 = tx*8
    const int ty  = tid >> 3;                        // row group  -> r0 = ty*4
    const int row0 = blockIdx.x * 64;

    float acc[4][8];
#pragma unroll
    for (int r = 0; r < 4; r++)
#pragma unroll
        for (int c = 0; c < 8; c++) acc[r][c] = 0.0f;

    for (int kt = 0; kt < KTOT; kt += 64) {
#pragma unroll
        for (int l = 0; l < 32; l++) {               // load A tile (transposed)
            int idx = l * 128 + tid;
            int k = idx & 63, r = idx >> 6;
            int row = row0 + r;
            xs[k][r] = (row < nrows) ? A[(long)row * KTOT + kt + k] : 0.0f;
        }
#pragma unroll
        for (int l = 0; l < 32; l++) {               // load W tile
            int idx = l * 128 + tid;
            int f = idx & 63, k = idx >> 6;
            ws[k][f] = W[(long)(kt + k) * HH + f];
        }
        __syncthreads();
#pragma unroll 16
        for (int k = 0; k < 64; k++) {
            float4 wa = *(const float4*)&ws[k][tx * 8];
            float4 wb = *(const float4*)&ws[k][tx * 8 + 4];
            float wv[8] = {wa.x, wa.y, wa.z, wa.w, wb.x, wb.y, wb.z, wb.w};
            float xv[4] = {xs[k][ty * 4 + 0], xs[k][ty * 4 + 1],
                           xs[k][ty * 4 + 2], xs[k][ty * 4 + 3]};
#pragma unroll
            for (int r = 0; r < 4; r++)
#pragma unroll
                for (int c = 0; c < 8; c++) acc[r][c] += xv[r] * wv[c];
        }
        __syncthreads();
    }

    float bv[8];
    if (BIAS_RELU) {
#pragma unroll
        for (int c = 0; c < 8; c++) bv[c] = bias[tx * 8 + c];
    }
#pragma unroll
    for (int r = 0; r < 4; r++) {
        int row = row0 + ty * 4 + r;
        if (row < nrows) {
            float o[8];
#pragma unroll
            for (int c = 0; c < 8; c++) {
                float v = acc[r][c];
                if (BIAS_RELU) v = fmaxf(v + bv[c], 0.0f);
                o[c] = v;
            }
            float4* op = (float4*)&out[(long)row * HH + tx * 8];
            op[0] = make_float4(o[0], o[1], o[2], o[3]);
            op[1] = make_float4(o[4], o[5], o[6], o[7]);
        }
    }
}

// ---------------- edge aggregation: warp per node, no atomics ----------------
// out[i] = relu( dinv[i]^2 * h[i] + sum_e val[e]*h[col[e]] + bias )
__global__ void k_agg(const float* __restrict__ h, const float* __restrict__ bias,
                      float* __restrict__ out) {
    int w    = (blockIdx.x * blockDim.x + threadIdx.x) >> 5;
    int lane = threadIdx.x & 31;
    if (w >= NN) return;
    float di = g_dinv[w];
    float sn = di * di;
    const float* hr = h + (long)w * HH;
    float a0 = sn * hr[lane];
    float a1 = sn * hr[lane + 32];
    int e = g_rowptr[w], e1 = g_rowptr[w + 1];
    for (; e + 2 <= e1; e += 2) {
        int   s0 = g_col[e],   s1 = g_col[e + 1];
        float v0 = g_val[e],   v1 = g_val[e + 1];
        const float* p0 = h + (long)s0 * HH;
        const float* p1 = h + (long)s1 * HH;
        a0 += v0 * p0[lane];      a1 += v0 * p0[lane + 32];
        a0 += v1 * p1[lane];      a1 += v1 * p1[lane + 32];
    }
    if (e < e1) {
        int s = g_col[e]; float v = g_val[e];
        const float* p = h + (long)s * HH;
        a0 += v * p[lane];        a1 += v * p[lane + 32];
    }
    out[(long)w * HH + lane]      = fmaxf(a0 + bias[lane], 0.0f);
    out[(long)w * HH + lane + 32] = fmaxf(a1 + bias[lane + 32], 0.0f);
}

// ---------------- head: logits = m @ Wm2 + bm2, softmax ----------------
__global__ void k_head(const float* __restrict__ m, const float* __restrict__ Wm2,
                       const float* __restrict__ bm2, float* __restrict__ out) {
    __shared__ __align__(16) float sW[HH * CC];
    __shared__ float sb[CC];
    int t = threadIdx.x;
    for (int i = t; i < HH * CC; i += blockDim.x) sW[i] = Wm2[i];
    if (t < CC) sb[t] = bm2[t];
    __syncthreads();
    int r = blockIdx.x * blockDim.x + t;
    if (r >= NN) return;

    float a[HH];
    const float4* mp = (const float4*)(m + (long)r * HH);
#pragma unroll
    for (int q = 0; q < 16; q++) {
        float4 v = mp[q];
        a[q * 4] = v.x; a[q * 4 + 1] = v.y; a[q * 4 + 2] = v.z; a[q * 4 + 3] = v.w;
    }
    float lg[CC];
#pragma unroll
    for (int c = 0; c < CC; c++) lg[c] = sb[c];
#pragma unroll
    for (int k = 0; k < HH; k++) {
        float av = a[k];
#pragma unroll
        for (int c4 = 0; c4 < 4; c4++) {
            float4 wv = *(const float4*)&sW[k * CC + c4 * 4];
            lg[c4 * 4 + 0] += av * wv.x;
            lg[c4 * 4 + 1] += av * wv.y;
            lg[c4 * 4 + 2] += av * wv.z;
            lg[c4 * 4 + 3] += av * wv.w;
        }
    }
    float mx = lg[0];
#pragma unroll
    for (int c = 1; c < CC; c++) mx = fmaxf(mx, lg[c]);
    float ssum = 0.0f;
#pragma unroll
    for (int c = 0; c < CC; c++) { lg[c] = __expf(lg[c] - mx); ssum += lg[c]; }
    float inv = 1.0f / ssum;
    float4* op = (float4*)(out + (long)r * CC);
#pragma unroll
    for (int c4 = 0; c4 < 4; c4++)
        op[c4] = make_float4(lg[c4 * 4] * inv, lg[c4 * 4 + 1] * inv,
                             lg[c4 * 4 + 2] * inv, lg[c4 * 4 + 3] * inv);
}

// ---------------- launch ----------------
extern "C" void kernel_launch(void* const* d_in, const int* in_sizes, int n_in,
                              void* d_out, int out_size) {
    const float* x   = (const float*)d_in[0];
    const void*  ei  = d_in[1];
    const float* ew  = (const float*)d_in[2];
    const float* W1  = (const float*)d_in[3];
    const float* b1  = (const float*)d_in[4];
    const float* W2  = (const float*)d_in[5];
    const float* b2  = (const float*)d_in[6];
    const float* Wm1 = (const float*)d_in[7];
    const float* bm1 = (const float*)d_in[8];
    const float* Wm2 = (const float*)d_in[9];
    const float* bm2 = (const float*)d_in[10];
    float* out = (float*)d_out;

    float *pA, *pB;
    cudaGetSymbolAddress((void**)&pA, g_bufA);
    cudaGetSymbolAddress((void**)&pB, g_bufB);

    // graph normalization + CSR build (per-launch, deterministic)
    k_detect<<<1, 32>>>((const unsigned int*)ei);
    k_init<<<(NN + 255) / 256, 256>>>();
    k_degcnt<<<(EE + 255) / 256, 256>>>(ei, ew);
    k_dinv<<<(NN + 255) / 256, 256>>>();
    k_scan<<<1, 1024>>>();
    k_scatter<<<(EE + 255) / 256, 256>>>(ei, ew);

    const int gemm_grid = (NN + 63) / 64;
    const int agg_grid  = (NN * 32 + 255) / 256;

    gemm64<INF, false><<<gemm_grid, 128>>>(x, W1, nullptr, pA, NN);   // h = xW1
    k_agg<<<agg_grid, 256>>>(pA, b1, pB);                             // conv1 + relu
    gemm64<HH, false><<<gemm_grid, 128>>>(pB, W2, nullptr, pA, NN);   // hW2
    k_agg<<<agg_grid, 256>>>(pA, b2, pB);                             // conv2 + relu
    gemm64<HH, true><<<gemm_grid, 128>>>(pB, Wm1, bm1, pA, NN);       // mlp hidden + relu
    k_head<<<(NN + 127) / 128, 128>>>(pA, Wm2, bm2, out);             // logits + softmax
}

// round 5
// speedup vs baseline: 1.9413x; 1.9413x over previous
#include <cuda_runtime.h>
#include <cuda_bf16.h>
#include <cstdint>

#define NN  100000
#define EE  1600000
#define INF 256
#define HH  64
#define CC  16

// ---------------- scratch (no allocations allowed -> device globals) ----------------
__device__ float g_bufA[(size_t)NN * HH];   // 25.6 MB
__device__ float g_bufB[(size_t)NN * HH];   // 25.6 MB
__device__ float g_deg[NN];
__device__ float g_dinv[NN];
__device__ int   g_cnt[NN];
__device__ int   g_rowptr[NN + 1];
__device__ int   g_cursor[NN];
__device__ int   g_col[EE];                 // 6.4 MB
__device__ float g_val[EE];                 // 6.4 MB
__device__ int   g_idx64;
__device__ int   g_blksum[128];
__device__ int   g_blkoff[128];

// edge_index may be int64 (reference declares it) or int32 (jax x64-disabled
// canonicalization). Detected at runtime; branch on device flag.
__device__ __forceinline__ int ld_idx(const void* ei, long long pos) {
    if (g_idx64)
        return (int)((const long long*)ei)[pos];
    return ((const int*)ei)[pos];
}

// init deg/cnt; thread 0 also detects index width: odd 32-bit words of the
// first 64 entries all zero iff int64 (indices < 100000 -> hi words 0).
__global__ void k_init(const unsigned int* ei) {
    int i = blockIdx.x * blockDim.x + threadIdx.x;
    if (i < NN) { g_deg[i] = 1.0f; g_cnt[i] = 0; }   // self-loop weight 1
    if (i == 0) {
        unsigned v = 0;
        for (int j = 0; j < 64; j++) v |= ei[2 * j + 1];
        g_idx64 = (v == 0) ? 1 : 0;
    }
}

__global__ void k_degcnt(const void* ei, const float* __restrict__ ew) {
    int e = blockIdx.x * blockDim.x + threadIdx.x;
    if (e < EE) {
        int d = ld_idx(ei, (long long)EE + e);       // dst row
        atomicAdd(&g_deg[d], ew[e]);
        atomicAdd(&g_cnt[d], 1);
    }
}

// ---- coalesced 3-phase exclusive scan of g_cnt -> g_rowptr/g_cursor ----
__global__ void k_scanA() {
    __shared__ int sm[1024];
    int t = threadIdx.x;
    int i = blockIdx.x * 1024 + t;
    int v = (i < NN) ? g_cnt[i] : 0;
    sm[t] = v;
    __syncthreads();
    for (int off = 1; off < 1024; off <<= 1) {
        int a = (t >= off) ? sm[t - off] : 0;
        __syncthreads();
        sm[t] += a;
        __syncthreads();
    }
    if (i < NN) g_rowptr[i] = sm[t] - v;             // block-local exclusive
    if (t == 1023) g_blksum[blockIdx.x] = sm[1023];
}

__global__ void k_scanB(int nblk) {
    __shared__ int sm[128];
    int t = threadIdx.x;
    int v = (t < nblk) ? g_blksum[t] : 0;
    sm[t] = v;
    __syncthreads();
    for (int off = 1; off < 128; off <<= 1) {
        int a = (t >= off) ? sm[t - off] : 0;
        __syncthreads();
        sm[t] += a;
        __syncthreads();
    }
    if (t < nblk) g_blkoff[t] = sm[t] - v;           // exclusive
}

__global__ void k_scanC() {
    int i = blockIdx.x * blockDim.x + threadIdx.x;
    if (i < NN) {
        int rp = g_rowptr[i] + g_blkoff[i >> 10];
        g_rowptr[i] = rp;
        g_cursor[i] = rp;
        g_dinv[i]   = rsqrtf(g_deg[i]);              // deg >= 1 always
    }
    if (i == 0) g_rowptr[NN] = EE;
}

__global__ void k_scatter(const void* ei, const float* __restrict__ ew) {
    int e = blockIdx.x * blockDim.x + threadIdx.x;
    if (e < EE) {
        int s = ld_idx(ei, e);
        int d = ld_idx(ei, (long long)EE + e);
        int pos = atomicAdd(&g_cursor[d], 1);
        g_col[pos] = s;
        g_val[pos] = g_dinv[s] * ew[e] * g_dinv[d];
    }
}

// ============ tensor-core GEMM via mma.sync (bf16 split, error-compensated) ============
// C[nrows,64] = A[nrows,KTOT] @ W[KTOT,64], fp32 in/out.
// A = Ahi+Alo, W = Whi+Wlo (bf16); D += Ahi*Whi + Ahi*Wlo + Alo*Whi.
// CTA: 128 rows x 64 cols, 4 warps; warp: 32x64 = 2(m16) x 8(n8) tiles, k16 steps.

#define APAD 72                               // bf16 row stride (conflict-free frags)
#define SM_AHI 0
#define SM_ALO (128 * APAD)                   // 9216
#define SM_BHI (2 * 128 * APAD)               // 18432
#define SM_BLO (2 * 128 * APAD + 64 * APAD)   // 23040
#define SMEM_ELEMS (2 * 128 * APAD + 2 * 64 * APAD)
#define SMEM_DYN (SMEM_ELEMS * 2)             // 55296 bytes

__device__ __forceinline__ void mma_bf16(float* c, const uint32_t* a,
                                         uint32_t b0, uint32_t b1) {
    asm volatile(
        "mma.sync.aligned.m16n8k16.row.col.f32.bf16.bf16.f32 "
        "{%0,%1,%2,%3}, {%4,%5,%6,%7}, {%8,%9}, {%0,%1,%2,%3};"
        : "+f"(c[0]), "+f"(c[1]), "+f"(c[2]), "+f"(c[3])
        : "r"(a[0]), "r"(a[1]), "r"(a[2]), "r"(a[3]), "r"(b0), "r"(b1));
}

template <int KTOT, bool BIAS_RELU>
__global__ void __launch_bounds__(128, 4)
gemm_tc(const float* __restrict__ A, const float* __restrict__ W,
        const float* __restrict__ bias, float* __restrict__ out, int nrows) {
    extern __shared__ __nv_bfloat16 sm[];
    __nv_bfloat16* Ahi = sm + SM_AHI;
    __nv_bfloat16* Alo = sm + SM_ALO;
    __nv_bfloat16* Bhi = sm + SM_BHI;
    __nv_bfloat16* Blo = sm + SM_BLO;

    const int tid  = threadIdx.x;
    const int wid  = tid >> 5;
    const int lane = tid & 31;
    const int g    = lane >> 2;               // 0..7
    const int tg   = lane & 3;                // 0..3
    const int row0 = blockIdx.x * 128;
    const int m0   = wid * 32;

    float acc[2][8][4];
#pragma unroll
    for (int mt = 0; mt < 2; mt++)
#pragma unroll
        for (int nt = 0; nt < 8; nt++)
#pragma unroll
            for (int j = 0; j < 4; j++) acc[mt][nt][j] = 0.0f;

    for (int kt = 0; kt < KTOT; kt += 64) {
        // ---- A tile [128 rows x 64 k] fp32 -> bf16 hi/lo ----
#pragma unroll
        for (int it = 0; it < 8; it++) {
            int chunk = it * 128 + tid;       // 1024 chunks of 8 elems
            int r  = chunk >> 3;
            int kc = (chunk & 7) * 8;
            int row = row0 + r;
            float v[8];
            if (row < nrows) {
                const float4* p = (const float4*)(A + (size_t)row * KTOT + kt + kc);
                float4 a = p[0], b = p[1];
                v[0] = a.x; v[1] = a.y; v[2] = a.z; v[3] = a.w;
                v[4] = b.x; v[5] = b.y; v[6] = b.z; v[7] = b.w;
            } else {
#pragma unroll
                for (int j = 0; j < 8; j++) v[j] = 0.0f;
            }
#pragma unroll
            for (int j = 0; j < 4; j++) {
                __nv_bfloat162 h, l;
                h.x = __float2bfloat16(v[2 * j]);
                h.y = __float2bfloat16(v[2 * j + 1]);
                l.x = __float2bfloat16(v[2 * j]     - __bfloat162float(h.x));
                l.y = __float2bfloat16(v[2 * j + 1] - __bfloat162float(h.y));
                *(__nv_bfloat162*)&Ahi[r * APAD + kc + 2 * j] = h;
                *(__nv_bfloat162*)&Alo[r * APAD + kc + 2 * j] = l;
            }
        }
        // ---- B tile: Bs[n][k] = W[kt+k][n], 64x64 ----
#pragma unroll
        for (int it = 0; it < 32; it++) {
            int idx = it * 128 + tid;         // 4096 elems, coalesced in n
            int n = idx & 63, k = idx >> 6;
            float w = W[(size_t)(kt + k) * HH + n];
            __nv_bfloat16 h = __float2bfloat16(w);
            Bhi[n * APAD + k] = h;
            Blo[n * APAD + k] = __float2bfloat16(w - __bfloat162float(h));
        }
        __syncthreads();

#pragma unroll
        for (int kc = 0; kc < 64; kc += 16) {
            uint32_t ah[2][4], al[2][4];
#pragma unroll
            for (int mt = 0; mt < 2; mt++) {
                int r = m0 + mt * 16 + g;
                ah[mt][0] = *(const uint32_t*)&Ahi[r * APAD + kc + tg * 2];
                ah[mt][1] = *(const uint32_t*)&Ahi[(r + 8) * APAD + kc + tg * 2];
                ah[mt][2] = *(const uint32_t*)&Ahi[r * APAD + kc + 8 + tg * 2];
                ah[mt][3] = *(const uint32_t*)&Ahi[(r + 8) * APAD + kc + 8 + tg * 2];
                al[mt][0] = *(const uint32_t*)&Alo[r * APAD + kc + tg * 2];
                al[mt][1] = *(const uint32_t*)&Alo[(r + 8) * APAD + kc + tg * 2];
                al[mt][2] = *(const uint32_t*)&Alo[r * APAD + kc + 8 + tg * 2];
                al[mt][3] = *(const uint32_t*)&Alo[(r + 8) * APAD + kc + 8 + tg * 2];
            }
#pragma unroll
            for (int nt = 0; nt < 8; nt++) {
                int n = nt * 8 + g;
                uint32_t bh0 = *(const uint32_t*)&Bhi[n * APAD + kc + tg * 2];
                uint32_t bh1 = *(const uint32_t*)&Bhi[n * APAD + kc + 8 + tg * 2];
                uint32_t bl0 = *(const uint32_t*)&Blo[n * APAD + kc + tg * 2];
                uint32_t bl1 = *(const uint32_t*)&Blo[n * APAD + kc + 8 + tg * 2];
#pragma unroll
                for (int mt = 0; mt < 2; mt++) {
                    mma_bf16(acc[mt][nt], ah[mt], bh0, bh1);   // hi*hi
                    mma_bf16(acc[mt][nt], ah[mt], bl0, bl1);   // hi*lo
                    mma_bf16(acc[mt][nt], al[mt], bh0, bh1);   // lo*hi
                }
            }
        }
        __syncthreads();
    }

    // ---- epilogue ----
#pragma unroll
    for (int mt = 0; mt < 2; mt++) {
        int r0 = row0 + m0 + mt * 16 + g;
        int r1 = r0 + 8;
#pragma unroll
        for (int nt = 0; nt < 8; nt++) {
            int c = nt * 8 + tg * 2;
            float v0 = acc[mt][nt][0], v1 = acc[mt][nt][1];
            float v2 = acc[mt][nt][2], v3 = acc[mt][nt][3];
            if (BIAS_RELU) {
                float b0 = __ldg(&bias[c]), b1 = __ldg(&bias[c + 1]);
                v0 = fmaxf(v0 + b0, 0.0f); v1 = fmaxf(v1 + b1, 0.0f);
                v2 = fmaxf(v2 + b0, 0.0f); v3 = fmaxf(v3 + b1, 0.0f);
            }
            if (r0 < nrows) *(float2*)&out[(size_t)r0 * HH + c] = make_float2(v0, v1);
            if (r1 < nrows) *(float2*)&out[(size_t)r1 * HH + c] = make_float2(v2, v3);
        }
    }
}

// ---------------- edge aggregation: warp per node, no atomics ----------------
__global__ void k_agg(const float* __restrict__ h, const float* __restrict__ bias,
                      float* __restrict__ out) {
    int w    = (blockIdx.x * blockDim.x + threadIdx.x) >> 5;
    int lane = threadIdx.x & 31;
    if (w >= NN) return;
    float di = g_dinv[w];
    float sn = di * di;
    const float* hr = h + (size_t)w * HH;
    float a0 = sn * hr[lane];
    float a1 = sn * hr[lane + 32];
    int e = g_rowptr[w], e1 = g_rowptr[w + 1];
    for (; e + 2 <= e1; e += 2) {
        int   s0 = g_col[e],   s1 = g_col[e + 1];
        float v0 = g_val[e],   v1 = g_val[e + 1];
        const float* p0 = h + (size_t)s0 * HH;
        const float* p1 = h + (size_t)s1 * HH;
        a0 += v0 * p0[lane];      a1 += v0 * p0[lane + 32];
        a0 += v1 * p1[lane];      a1 += v1 * p1[lane + 32];
    }
    if (e < e1) {
        int s = g_col[e]; float v = g_val[e];
        const float* p = h + (size_t)s * HH;
        a0 += v * p[lane];        a1 += v * p[lane + 32];
    }
    out[(size_t)w * HH + lane]      = fmaxf(a0 + bias[lane], 0.0f);
    out[(size_t)w * HH + lane + 32] = fmaxf(a1 + bias[lane + 32], 0.0f);
}

// ---------------- head: logits = m @ Wm2 + bm2, softmax ----------------
__global__ void k_head(const float* __restrict__ m, const float* __restrict__ Wm2,
                       const float* __restrict__ bm2, float* __restrict__ out) {
    __shared__ __align__(16) float sW[HH * CC];
    __shared__ float sb[CC];
    int t = threadIdx.x;
    for (int i = t; i < HH * CC; i += blockDim.x) sW[i] = Wm2[i];
    if (t < CC) sb[t] = bm2[t];
    __syncthreads();
    int r = blockIdx.x * blockDim.x + t;
    if (r >= NN) return;

    float a[HH];
    const float4* mp = (const float4*)(m + (size_t)r * HH);
#pragma unroll
    for (int q = 0; q < 16; q++) {
        float4 v = mp[q];
        a[q * 4] = v.x; a[q * 4 + 1] = v.y; a[q * 4 + 2] = v.z; a[q * 4 + 3] = v.w;
    }
    float lg[CC];
#pragma unroll
    for (int c = 0; c < CC; c++) lg[c] = sb[c];
#pragma unroll
    for (int k = 0; k < HH; k++) {
        float av = a[k];
#pragma unroll
        for (int c4 = 0; c4 < 4; c4++) {
            float4 wv = *(const float4*)&sW[k * CC + c4 * 4];
            lg[c4 * 4 + 0] += av * wv.x;
            lg[c4 * 4 + 1] += av * wv.y;
            lg[c4 * 4 + 2] += av * wv.z;
            lg[c4 * 4 + 3] += av * wv.w;
        }
    }
    float mx = lg[0];
#pragma unroll
    for (int c = 1; c < CC; c++) mx = fmaxf(mx, lg[c]);
    float ssum = 0.0f;
#pragma unroll
    for (int c = 0; c < CC; c++) { lg[c] = __expf(lg[c] - mx); ssum += lg[c]; }
    float inv = 1.0f / ssum;
    float4* op = (float4*)(out + (size_t)r * CC);
#pragma unroll
    for (int c4 = 0; c4 < 4; c4++)
        op[c4] = make_float4(lg[c4 * 4] * inv, lg[c4 * 4 + 1] * inv,
                             lg[c4 * 4 + 2] * inv, lg[c4 * 4 + 3] * inv);
}

// ---------------- launch ----------------
extern "C" void kernel_launch(void* const* d_in, const int* in_sizes, int n_in,
                              void* d_out, int out_size) {
    const float* x   = (const float*)d_in[0];
    const void*  ei  = d_in[1];
    const float* ew  = (const float*)d_in[2];
    const float* W1  = (const float*)d_in[3];
    const float* b1  = (const float*)d_in[4];
    const float* W2  = (const float*)d_in[5];
    const float* b2  = (const float*)d_in[6];
    const float* Wm1 = (const float*)d_in[7];
    const float* bm1 = (const float*)d_in[8];
    const float* Wm2 = (const float*)d_in[9];
    const float* bm2 = (const float*)d_in[10];
    float* out = (float*)d_out;

    float *pA, *pB;
    cudaGetSymbolAddress((void**)&pA, g_bufA);
    cudaGetSymbolAddress((void**)&pB, g_bufB);

    cudaFuncSetAttribute(gemm_tc<INF, false>, cudaFuncAttributeMaxDynamicSharedMemorySize, SMEM_DYN);
    cudaFuncSetAttribute(gemm_tc<HH,  false>, cudaFuncAttributeMaxDynamicSharedMemorySize, SMEM_DYN);
    cudaFuncSetAttribute(gemm_tc<HH,  true >, cudaFuncAttributeMaxDynamicSharedMemorySize, SMEM_DYN);

    const int nblk = (NN + 1023) / 1024;             // 98

    // graph normalization + CSR build (per-launch, deterministic)
    k_init<<<(NN + 255) / 256, 256>>>((const unsigned int*)ei);
    k_degcnt<<<(EE + 255) / 256, 256>>>(ei, ew);
    k_scanA<<<nblk, 1024>>>();
    k_scanB<<<1, 128>>>(nblk);
    k_scanC<<<(NN + 255) / 256, 256>>>();
    k_scatter<<<(EE + 255) / 256, 256>>>(ei, ew);

    const int gemm_grid = (NN + 127) / 128;
    const int agg_grid  = (NN * 32 + 255) / 256;

    gemm_tc<INF, false><<<gemm_grid, 128, SMEM_DYN>>>(x,  W1,  nullptr, pA, NN);  // h = xW1
    k_agg<<<agg_grid, 256>>>(pA, b1, pB);                                         // conv1+relu
    gemm_tc<HH, false><<<gemm_grid, 128, SMEM_DYN>>>(pB, W2,  nullptr, pA, NN);   // hW2
    k_agg<<<agg_grid, 256>>>(pA, b2, pB);                                         // conv2+relu
    gemm_tc<HH, true ><<<gemm_grid, 128, SMEM_DYN>>>(pB, Wm1, bm1,     pA, NN);   // mlp+relu
    k_head<<<(NN + 127) / 128, 128>>>(pA, Wm2, bm2, out);                         // softmax
}

// round 6
// speedup vs baseline: 1.9887x; 1.0244x over previous
#include <cuda_runtime.h>
#include <cuda_bf16.h>
#include <cuda_fp16.h>
#include <cstdint>

#define NN  100000
#define EE  1600000
#define INF 256
#define HH  64
#define CC  16

// ---------------- scratch (no allocations allowed -> device globals) ----------------
__device__ float g_bufA[(size_t)NN * HH];   // 25.6 MB (also holds fp16 h as 12.8 MB)
__device__ float g_bufB[(size_t)NN * HH];   // 25.6 MB
__device__ float g_deg[NN];
__device__ float g_dinv[NN];
__device__ int   g_cnt[NN];
__device__ int   g_rowptr[NN + 1];
__device__ int   g_cursor[NN];
__device__ int   g_col[EE];                 // 6.4 MB
__device__ float g_val[EE];                 // 6.4 MB
__device__ int   g_idx64;
__device__ int   g_blksum[128];
__device__ int   g_blkoff[128];
__device__ int   g_arrive;

// edge_index may be int64 (reference declares it) or int32 (jax x64-disabled
// canonicalization). Detected at runtime; branch on device flag.
__device__ __forceinline__ int ld_idx(const void* ei, long long pos) {
    if (g_idx64)
        return (int)((const long long*)ei)[pos];
    return ((const int*)ei)[pos];
}

// init deg/cnt; thread 0 detects index width: odd 32-bit words of the first 64
// entries all zero iff int64 (indices < 100000 -> hi words 0).
__global__ void k_init(const unsigned int* ei) {
    int i = blockIdx.x * blockDim.x + threadIdx.x;
    if (i < NN) { g_deg[i] = 1.0f; g_cnt[i] = 0; }   // self-loop weight 1
    if (i == 0) {
        unsigned v = 0;
        for (int j = 0; j < 64; j++) v |= ei[2 * j + 1];
        g_idx64 = (v == 0) ? 1 : 0;
    }
    if (i == 2) g_arrive = 0;
}

__global__ void k_degcnt(const void* ei, const float* __restrict__ ew) {
    int e = blockIdx.x * blockDim.x + threadIdx.x;
    if (e < EE) {
        int d = ld_idx(ei, (long long)EE + e);       // dst row
        atomicAdd(&g_deg[d], ew[e]);
        atomicAdd(&g_cnt[d], 1);
    }
}

// ---- scan phase A: block-local scan; ticketed last block scans block sums ----
__global__ void k_scanA() {
    __shared__ int smv[1024];
    __shared__ int sb[128];
    __shared__ int s_last;
    int t = threadIdx.x;
    int i = blockIdx.x * 1024 + t;
    int v = (i < NN) ? g_cnt[i] : 0;
    smv[t] = v;
    __syncthreads();
    for (int off = 1; off < 1024; off <<= 1) {
        int a = (t >= off) ? smv[t - off] : 0;
        __syncthreads();
        smv[t] += a;
        __syncthreads();
    }
    if (i < NN) g_rowptr[i] = smv[t] - v;            // block-local exclusive
    if (t == 1023) g_blksum[blockIdx.x] = smv[1023];
    __threadfence();
    __syncthreads();
    if (t == 0) s_last = (atomicAdd(&g_arrive, 1) == (int)gridDim.x - 1);
    __syncthreads();
    if (s_last) {                                    // uniform branch
        int nb = (int)gridDim.x;
        int bv = (t < 128 && t < nb) ? g_blksum[t] : 0;
        if (t < 128) sb[t] = bv;
        __syncthreads();
        for (int off = 1; off < 128; off <<= 1) {
            int a = (t < 128 && t >= off) ? sb[t - off] : 0;
            __syncthreads();
            if (t < 128) sb[t] += a;
            __syncthreads();
        }
        if (t < nb) g_blkoff[t] = sb[t] - bv;        // exclusive
    }
}

__global__ void k_scanC() {
    int i = blockIdx.x * blockDim.x + threadIdx.x;
    if (i < NN) {
        int rp = g_rowptr[i] + g_blkoff[i >> 10];
        g_rowptr[i] = rp;
        g_cursor[i] = rp;
        g_dinv[i]   = rsqrtf(g_deg[i]);              // deg >= 1 always
    }
    if (i == 0) g_rowptr[NN] = EE;
}

__global__ void k_scatter(const void* ei, const float* __restrict__ ew) {
    int e = blockIdx.x * blockDim.x + threadIdx.x;
    if (e < EE) {
        int s = ld_idx(ei, e);
        int d = ld_idx(ei, (long long)EE + e);
        int pos = atomicAdd(&g_cursor[d], 1);
        g_col[pos] = s;
        g_val[pos] = g_dinv[s] * ew[e] * g_dinv[d];
    }
}

// ============ tensor-core GEMM via mma.sync (bf16 split, error-compensated) ============
// C[nrows,64] = A[nrows,KTOT] @ W[KTOT,64], fp32 in, fp16 or fp32 out.
// A = Ahi+Alo, W = Whi+Wlo (bf16); D += Ahi*Whi + Ahi*Wlo + Alo*Whi.
// CTA: 128 rows x 64 cols, 4 warps; warp: 32x64 = 2(m16) x 8(n8) tiles, k16 steps.

#define APAD 72                               // bf16 row stride (conflict-free frags)
#define SM_AHI 0
#define SM_ALO (128 * APAD)
#define SM_BHI (2 * 128 * APAD)
#define SM_BLO (2 * 128 * APAD + 64 * APAD)
#define SMEM_ELEMS (2 * 128 * APAD + 2 * 64 * APAD)
#define SMEM_DYN (SMEM_ELEMS * 2)             // 55296 bytes

__device__ __forceinline__ void mma_bf16(float* c, const uint32_t* a,
                                         uint32_t b0, uint32_t b1) {
    asm volatile(
        "mma.sync.aligned.m16n8k16.row.col.f32.bf16.bf16.f32 "
        "{%0,%1,%2,%3}, {%4,%5,%6,%7}, {%8,%9}, {%0,%1,%2,%3};"
        : "+f"(c[0]), "+f"(c[1]), "+f"(c[2]), "+f"(c[3])
        : "r"(a[0]), "r"(a[1]), "r"(a[2]), "r"(a[3]), "r"(b0), "r"(b1));
}

// shared mainloop body: fills acc[2][8][4] for this warp
template <int KTOT>
__device__ __forceinline__ void gemm_mainloop(
    const float* __restrict__ A, const float* __restrict__ W, int nrows,
    char* dsm, int row0, int tid, int wid, int lane, int g, int tg,
    float acc[2][8][4]) {
    __nv_bfloat16* Ahi = (__nv_bfloat16*)dsm + SM_AHI;
    __nv_bfloat16* Alo = (__nv_bfloat16*)dsm + SM_ALO;
    __nv_bfloat16* Bhi = (__nv_bfloat16*)dsm + SM_BHI;
    __nv_bfloat16* Blo = (__nv_bfloat16*)dsm + SM_BLO;
    const int m0 = wid * 32;

    for (int kt = 0; kt < KTOT; kt += 64) {
        // ---- A tile [128 rows x 64 k] fp32 -> bf16 hi/lo ----
#pragma unroll
        for (int it = 0; it < 8; it++) {
            int chunk = it * 128 + tid;       // 1024 chunks of 8 elems
            int r  = chunk >> 3;
            int kc = (chunk & 7) * 8;
            int row = row0 + r;
            float v[8];
            if (row < nrows) {
                const float4* p = (const float4*)(A + (size_t)row * KTOT + kt + kc);
                float4 a = p[0], b = p[1];
                v[0] = a.x; v[1] = a.y; v[2] = a.z; v[3] = a.w;
                v[4] = b.x; v[5] = b.y; v[6] = b.z; v[7] = b.w;
            } else {
#pragma unroll
                for (int j = 0; j < 8; j++) v[j] = 0.0f;
            }
#pragma unroll
            for (int j = 0; j < 4; j++) {
                __nv_bfloat162 h, l;
                h.x = __float2bfloat16(v[2 * j]);
                h.y = __float2bfloat16(v[2 * j + 1]);
                l.x = __float2bfloat16(v[2 * j]     - __bfloat162float(h.x));
                l.y = __float2bfloat16(v[2 * j + 1] - __bfloat162float(h.y));
                *(__nv_bfloat162*)&Ahi[r * APAD + kc + 2 * j] = h;
                *(__nv_bfloat162*)&Alo[r * APAD + kc + 2 * j] = l;
            }
        }
        // ---- B tile: Bs[n][k] = W[kt+k][n], 64x64 ----
#pragma unroll
        for (int it = 0; it < 32; it++) {
            int idx = it * 128 + tid;         // coalesced in n
            int n = idx & 63, k = idx >> 6;
            float w = W[(size_t)(kt + k) * HH + n];
            __nv_bfloat16 h = __float2bfloat16(w);
            Bhi[n * APAD + k] = h;
            Blo[n * APAD + k] = __float2bfloat16(w - __bfloat162float(h));
        }
        __syncthreads();

#pragma unroll
        for (int kc = 0; kc < 64; kc += 16) {
            uint32_t ah[2][4], al[2][4];
#pragma unroll
            for (int mt = 0; mt < 2; mt++) {
                int r = m0 + mt * 16 + g;
                ah[mt][0] = *(const uint32_t*)&Ahi[r * APAD + kc + tg * 2];
                ah[mt][1] = *(const uint32_t*)&Ahi[(r + 8) * APAD + kc + tg * 2];
                ah[mt][2] = *(const uint32_t*)&Ahi[r * APAD + kc + 8 + tg * 2];
                ah[mt][3] = *(const uint32_t*)&Ahi[(r + 8) * APAD + kc + 8 + tg * 2];
                al[mt][0] = *(const uint32_t*)&Alo[r * APAD + kc + tg * 2];
                al[mt][1] = *(const uint32_t*)&Alo[(r + 8) * APAD + kc + tg * 2];
                al[mt][2] = *(const uint32_t*)&Alo[r * APAD + kc + 8 + tg * 2];
                al[mt][3] = *(const uint32_t*)&Alo[(r + 8) * APAD + kc + 8 + tg * 2];
            }
#pragma unroll
            for (int nt = 0; nt < 8; nt++) {
                int n = nt * 8 + g;
                uint32_t bh0 = *(const uint32_t*)&Bhi[n * APAD + kc + tg * 2];
                uint32_t bh1 = *(const uint32_t*)&Bhi[n * APAD + kc + 8 + tg * 2];
                uint32_t bl0 = *(const uint32_t*)&Blo[n * APAD + kc + tg * 2];
                uint32_t bl1 = *(const uint32_t*)&Blo[n * APAD + kc + 8 + tg * 2];
#pragma unroll
                for (int mt = 0; mt < 2; mt++) {
                    mma_bf16(acc[mt][nt], ah[mt], bh0, bh1);   // hi*hi
                    mma_bf16(acc[mt][nt], ah[mt], bl0, bl1);   // hi*lo
                    mma_bf16(acc[mt][nt], al[mt], bh0, bh1);   // lo*hi
                }
            }
        }
        __syncthreads();
    }
}

// plain GEMM, fp16 output (feeds aggregation)
template <int KTOT>
__global__ void __launch_bounds__(128, 4)
gemm_tc(const float* __restrict__ A, const float* __restrict__ W,
        __half2* __restrict__ out, int nrows) {
    extern __shared__ char dsm[];
    const int tid = threadIdx.x, wid = tid >> 5, lane = tid & 31;
    const int g = lane >> 2, tg = lane & 3;
    const int row0 = blockIdx.x * 128;

    float acc[2][8][4];
#pragma unroll
    for (int mt = 0; mt < 2; mt++)
#pragma unroll
        for (int nt = 0; nt < 8; nt++)
#pragma unroll
            for (int j = 0; j < 4; j++) acc[mt][nt][j] = 0.0f;

    gemm_mainloop<KTOT>(A, W, nrows, dsm, row0, tid, wid, lane, g, tg, acc);

#pragma unroll
    for (int mt = 0; mt < 2; mt++) {
        int r0 = row0 + wid * 32 + mt * 16 + g;
        int r1 = r0 + 8;
#pragma unroll
        for (int nt = 0; nt < 8; nt++) {
            int h2c = nt * 4 + tg;            // half2 column
            if (r0 < nrows)
                out[(size_t)r0 * 32 + h2c] = __floats2half2_rn(acc[mt][nt][0], acc[mt][nt][1]);
            if (r1 < nrows)
                out[(size_t)r1 * 32 + h2c] = __floats2half2_rn(acc[mt][nt][2], acc[mt][nt][3]);
        }
    }
}

// GEMM (K=64) + bias/relu + fused MLP head (logits @ Wm2 + bm2, softmax)
__global__ void __launch_bounds__(128, 4)
gemm_head(const float* __restrict__ A, const float* __restrict__ Wm1,
          const float* __restrict__ bm1, const float* __restrict__ Wm2,
          const float* __restrict__ bm2, float* __restrict__ out, int nrows) {
    extern __shared__ char dsm[];
    const int tid = threadIdx.x, wid = tid >> 5, lane = tid & 31;
    const int g = lane >> 2, tg = lane & 3;
    const int row0 = blockIdx.x * 128;

    float acc[2][8][4];
#pragma unroll
    for (int mt = 0; mt < 2; mt++)
#pragma unroll
        for (int nt = 0; nt < 8; nt++)
#pragma unroll
            for (int j = 0; j < 4; j++) acc[mt][nt][j] = 0.0f;

    gemm_mainloop<HH>(A, Wm1, nrows, dsm, row0, tid, wid, lane, g, tg, acc);

    // stage relu(acc + bm1) into smem [128][65] (reuses dead tile memory)
    float* st  = (float*)dsm;                 // 128*65*4 = 33280 B
    float* sW  = st + 128 * 65;               // 64*16*4  = 4096 B
    float* sbv = sW + 64 * 16;                // 16*4 B    (total 37440 < 55296)
#pragma unroll
    for (int mt = 0; mt < 2; mt++) {
        int rl0 = wid * 32 + mt * 16 + g;
#pragma unroll
        for (int nt = 0; nt < 8; nt++) {
            int c = nt * 8 + tg * 2;
            float b0 = __ldg(&bm1[c]), b1 = __ldg(&bm1[c + 1]);
            st[rl0 * 65 + c]           = fmaxf(acc[mt][nt][0] + b0, 0.0f);
            st[rl0 * 65 + c + 1]       = fmaxf(acc[mt][nt][1] + b1, 0.0f);
            st[(rl0 + 8) * 65 + c]     = fmaxf(acc[mt][nt][2] + b0, 0.0f);
            st[(rl0 + 8) * 65 + c + 1] = fmaxf(acc[mt][nt][3] + b1, 0.0f);
        }
    }
    for (int i = tid; i < HH * CC; i += 128) sW[i] = Wm2[i];
    if (tid < CC) sbv[tid] = bm2[tid];
    __syncthreads();

    int r = row0 + tid;                       // one row per thread
    if (r < nrows) {
        float lg[CC];
#pragma unroll
        for (int c = 0; c < CC; c++) lg[c] = sbv[c];
        const float* mrow = st + tid * 65;    // stride 65 -> conflict-free
#pragma unroll
        for (int k = 0; k < HH; k++) {
            float av = mrow[k];
#pragma unroll
            for (int c = 0; c < CC; c++) lg[c] += av * sW[k * CC + c];
        }
        float mx = lg[0];
#pragma unroll
        for (int c = 1; c < CC; c++) mx = fmaxf(mx, lg[c]);
        float ssum = 0.0f;
#pragma unroll
        for (int c = 0; c < CC; c++) { lg[c] = __expf(lg[c] - mx); ssum += lg[c]; }
        float inv = 1.0f / ssum;
        float4* op = (float4*)(out + (size_t)r * CC);
#pragma unroll
        for (int c4 = 0; c4 < 4; c4++)
            op[c4] = make_float4(lg[c4 * 4] * inv, lg[c4 * 4 + 1] * inv,
                                 lg[c4 * 4 + 2] * inv, lg[c4 * 4 + 3] * inv);
    }
}

// ------- edge aggregation: warp per node, fp16 gather, fp32 accumulate -------
// out[i] = relu( dinv[i]^2 * h[i] + sum_e val[e]*h[col[e]] + bias )
__global__ void k_agg16(const __half2* __restrict__ h, const float* __restrict__ bias,
                        float* __restrict__ out) {
    int w    = (blockIdx.x * blockDim.x + threadIdx.x) >> 5;
    int lane = threadIdx.x & 31;
    if (w >= NN) return;
    float di = g_dinv[w];
    float sn = di * di;
    float2 hv = __half22float2(h[(size_t)w * 32 + lane]);
    float a0 = sn * hv.x, a1 = sn * hv.y;
    int e = g_rowptr[w], e1 = g_rowptr[w + 1];
    for (; e + 4 <= e1; e += 4) {
        int   s0 = g_col[e],     s1 = g_col[e + 1];
        int   s2 = g_col[e + 2], s3 = g_col[e + 3];
        float v0 = g_val[e],     v1 = g_val[e + 1];
        float v2 = g_val[e + 2], v3 = g_val[e + 3];
        float2 p0 = __half22float2(h[(size_t)s0 * 32 + lane]);
        float2 p1 = __half22float2(h[(size_t)s1 * 32 + lane]);
        float2 p2 = __half22float2(h[(size_t)s2 * 32 + lane]);
        float2 p3 = __half22float2(h[(size_t)s3 * 32 + lane]);
        a0 += v0 * p0.x; a1 += v0 * p0.y;
        a0 += v1 * p1.x; a1 += v1 * p1.y;
        a0 += v2 * p2.x; a1 += v2 * p2.y;
        a0 += v3 * p3.x; a1 += v3 * p3.y;
    }
    for (; e < e1; e++) {
        int s = g_col[e]; float v = g_val[e];
        float2 p = __half22float2(h[(size_t)s * 32 + lane]);
        a0 += v * p.x; a1 += v * p.y;
    }
    float2 bv = *(const float2*)&bias[2 * lane];
    *(float2*)&out[(size_t)w * HH + 2 * lane] =
        make_float2(fmaxf(a0 + bv.x, 0.0f), fmaxf(a1 + bv.y, 0.0f));
}

// ---------------- launch ----------------
extern "C" void kernel_launch(void* const* d_in, const int* in_sizes, int n_in,
                              void* d_out, int out_size) {
    const float* x   = (const float*)d_in[0];
    const void*  ei  = d_in[1];
    const float* ew  = (const float*)d_in[2];
    const float* W1  = (const float*)d_in[3];
    const float* b1  = (const float*)d_in[4];
    const float* W2  = (const float*)d_in[5];
    const float* b2  = (const float*)d_in[6];
    const float* Wm1 = (const float*)d_in[7];
    const float* bm1 = (const float*)d_in[8];
    const float* Wm2 = (const float*)d_in[9];
    const float* bm2 = (const float*)d_in[10];
    float* out = (float*)d_out;

    float *pA, *pB;
    cudaGetSymbolAddress((void**)&pA, g_bufA);
    cudaGetSymbolAddress((void**)&pB, g_bufB);
    __half2* pA16 = (__half2*)pA;

    static cudaStream_t s2 = 0;
    static cudaEvent_t evA = 0, evB = 0;
    if (!s2) {
        cudaStreamCreateWithFlags(&s2, cudaStreamNonBlocking);
        cudaEventCreateWithFlags(&evA, cudaEventDisableTiming);
        cudaEventCreateWithFlags(&evB, cudaEventDisableTiming);
        cudaFuncSetAttribute(gemm_tc<INF>, cudaFuncAttributeMaxDynamicSharedMemorySize, SMEM_DYN);
        cudaFuncSetAttribute(gemm_tc<HH>,  cudaFuncAttributeMaxDynamicSharedMemorySize, SMEM_DYN);
        cudaFuncSetAttribute(gemm_head,    cudaFuncAttributeMaxDynamicSharedMemorySize, SMEM_DYN);
    }

    const int gemm_grid = (NN + 127) / 128;
    const int agg_grid  = (NN * 32 + 255) / 256;
    const int nblk      = (NN + 1023) / 1024;        // 98

    // fork: GEMM1 (x @ W1 -> fp16 h) runs concurrently with CSR build
    cudaEventRecord(evA, 0);
    cudaStreamWaitEvent(s2, evA, 0);
    gemm_tc<INF><<<gemm_grid, 128, SMEM_DYN, s2>>>(x, W1, pA16, NN);
    cudaEventRecord(evB, s2);

    // CSR build on main stream
    k_init<<<(NN + 255) / 256, 256>>>((const unsigned int*)ei);
    k_degcnt<<<(EE + 255) / 256, 256>>>(ei, ew);
    k_scanA<<<nblk, 1024>>>();
    k_scanC<<<(NN + 255) / 256, 256>>>();
    k_scatter<<<(EE + 255) / 256, 256>>>(ei, ew);

    cudaStreamWaitEvent(0, evB, 0);                  // join GEMM1

    k_agg16<<<agg_grid, 256>>>(pA16, b1, pB);                         // conv1+relu (fp32)
    gemm_tc<HH><<<gemm_grid, 128, SMEM_DYN>>>(pB, W2, pA16, NN);      // h2 = conv1 @ W2 (fp16)
    k_agg16<<<agg_grid, 256>>>(pA16, b2, pB);                         // conv2+relu (fp32)
    gemm_head<<<gemm_grid, 128, SMEM_DYN>>>(pB, Wm1, bm1, Wm2, bm2, out, NN);
}

// round 7
// speedup vs baseline: 2.2981x; 1.1556x over previous
#include <cuda_runtime.h>
#include <cuda_bf16.h>
#include <cuda_fp16.h>
#include <cstdint>

#define NN  100000
#define EE  1600000
#define INF 256
#define HH  64
#define CC  16

// ---------------- scratch (no allocations allowed -> device globals) ----------------
__device__ float g_bufA[(size_t)NN * HH];   // 25.6 MB (fp16 h lives here as 12.8 MB)
__device__ float g_bufB[(size_t)NN * HH];   // 25.6 MB
__device__ float g_deg[NN];                 // weighted in-degree (excl. self loop)
__device__ float g_dinv[NN];
__device__ int   g_cnt[NN];
__device__ int   g_rowptr[NN + 1];
__device__ int   g_rank[EE];                // rank of edge within its dst bucket
__device__ uint2 g_edge[EE];                // packed (src, val) 8B
__device__ int   g_idx64;
__device__ int   g_blksum[128];
__device__ int   g_blkoff[128];
__device__ int   g_arrive;

// edge_index may be int64 (reference declares it) or int32 (jax x64-disabled
// canonicalization). Detected at runtime; branch on device flag.
__device__ __forceinline__ int ld_idx(const void* ei, long long pos) {
    if (g_idx64)
        return (int)((const long long*)ei)[pos];
    return ((const int*)ei)[pos];
}

// odd 32-bit words of the first 64 entries all zero iff int64 (indices < 1e5).
__global__ void k_detect(const unsigned int* ei) {
    if (threadIdx.x == 0) {
        unsigned v = 0;
        for (int j = 0; j < 64; j++) v |= ei[2 * j + 1];
        g_idx64 = (v == 0) ? 1 : 0;
    }
}

// pass 1 over edges: weighted degree (no-return reduce) + count (return = rank)
__global__ void k_degcnt(const void* ei, const float* __restrict__ ew) {
    int e = blockIdx.x * blockDim.x + threadIdx.x;
    if (e < EE) {
        int d = ld_idx(ei, (long long)EE + e);       // dst row
        atomicAdd(&g_deg[d], ew[e]);                 // result unused -> RED
        g_rank[e] = atomicAdd(&g_cnt[d], 1);
    }
}

// ---- scan phase A: shuffle block scan; ticketed last block scans block sums ----
__global__ void k_scanA() {
    __shared__ int wsum[32];
    __shared__ int sb[128];
    __shared__ int s_last;
    const int t    = threadIdx.x;
    const int lane = t & 31;
    const int warp = t >> 5;
    int i = blockIdx.x * 1024 + t;
    int v = (i < NN) ? g_cnt[i] : 0;

    int x = v;
#pragma unroll
    for (int off = 1; off < 32; off <<= 1) {
        int y = __shfl_up_sync(0xffffffff, x, off);
        if (lane >= off) x += y;
    }
    if (lane == 31) wsum[warp] = x;
    __syncthreads();
    if (warp == 0) {
        int w = (lane < 32) ? wsum[lane] : 0;
#pragma unroll
        for (int off = 1; off < 32; off <<= 1) {
            int y = __shfl_up_sync(0xffffffff, w, off);
            if (lane >= off) w += y;
        }
        wsum[lane] = w;                              // inclusive warp sums
    }
    __syncthreads();
    int incl = x + (warp ? wsum[warp - 1] : 0);
    if (i < NN) g_rowptr[i] = incl - v;              // block-local exclusive
    if (t == 1023) g_blksum[blockIdx.x] = incl;
    __threadfence();
    __syncthreads();
    if (t == 0) s_last = (atomicAdd(&g_arrive, 1) == (int)gridDim.x - 1);
    __syncthreads();
    if (s_last) {                                    // uniform branch
        int nb = (int)gridDim.x;
        int bv = (t < 128 && t < nb) ? g_blksum[t] : 0;
        if (t < 128) sb[t] = bv;
        __syncthreads();
        for (int off = 1; off < 128; off <<= 1) {
            int a = (t < 128 && t >= off) ? sb[t - off] : 0;
            __syncthreads();
            if (t < 128) sb[t] += a;
            __syncthreads();
        }
        if (t < nb) g_blkoff[t] = sb[t] - bv;        // exclusive
    }
}

__global__ void k_scanC() {
    int i = blockIdx.x * blockDim.x + threadIdx.x;
    if (i < NN) {
        g_rowptr[i] = g_rowptr[i] + g_blkoff[i >> 10];
        g_dinv[i]   = rsqrtf(1.0f + g_deg[i]);       // +1 = self-loop weight
    }
    if (i == 0) g_rowptr[NN] = EE;
}

// pass 2 over edges: atomic-free placement via rowptr + rank, packed 8B store.
// stored val = dinv[src]*w  (dinv[dst] applied once per node in agg)
__global__ void k_scatter(const void* ei, const float* __restrict__ ew) {
    int e = blockIdx.x * blockDim.x + threadIdx.x;
    if (e < EE) {
        int s = ld_idx(ei, e);
        int d = ld_idx(ei, (long long)EE + e);
        int pos = g_rowptr[d] + g_rank[e];
        float v = g_dinv[s] * ew[e];
        g_edge[pos] = make_uint2((unsigned)s, __float_as_uint(v));
    }
}

// ============ tensor-core GEMM via mma.sync (bf16 split, error-compensated) ============
// C[nrows,64] = A[nrows,KTOT] @ W[KTOT,64], fp32 in, fp16 or fp32 out.
// A = Ahi+Alo, W = Whi+Wlo (bf16); D += Ahi*Whi + Ahi*Wlo + Alo*Whi.
// CTA: 128 rows x 64 cols, 4 warps; warp: 32x64 = 2(m16) x 8(n8) tiles, k16 steps.

#define APAD 72                               // bf16 row stride (conflict-free frags)
#define SM_AHI 0
#define SM_ALO (128 * APAD)
#define SM_BHI (2 * 128 * APAD)
#define SM_BLO (2 * 128 * APAD + 64 * APAD)
#define SMEM_ELEMS (2 * 128 * APAD + 2 * 64 * APAD)
#define SMEM_DYN (SMEM_ELEMS * 2)             // 55296 bytes

__device__ __forceinline__ void mma_bf16(float* c, const uint32_t* a,
                                         uint32_t b0, uint32_t b1) {
    asm volatile(
        "mma.sync.aligned.m16n8k16.row.col.f32.bf16.bf16.f32 "
        "{%0,%1,%2,%3}, {%4,%5,%6,%7}, {%8,%9}, {%0,%1,%2,%3};"
        : "+f"(c[0]), "+f"(c[1]), "+f"(c[2]), "+f"(c[3])
        : "r"(a[0]), "r"(a[1]), "r"(a[2]), "r"(a[3]), "r"(b0), "r"(b1));
}

// shared mainloop body: fills acc[2][8][4] for this warp
template <int KTOT>
__device__ __forceinline__ void gemm_mainloop(
    const float* __restrict__ A, const float* __restrict__ W, int nrows,
    char* dsm, int row0, int tid, int wid, int lane, int g, int tg,
    float acc[2][8][4]) {
    __nv_bfloat16* Ahi = (__nv_bfloat16*)dsm + SM_AHI;
    __nv_bfloat16* Alo = (__nv_bfloat16*)dsm + SM_ALO;
    __nv_bfloat16* Bhi = (__nv_bfloat16*)dsm + SM_BHI;
    __nv_bfloat16* Blo = (__nv_bfloat16*)dsm + SM_BLO;
    const int m0 = wid * 32;

    for (int kt = 0; kt < KTOT; kt += 64) {
        // ---- A tile [128 rows x 64 k] fp32 -> bf16 hi/lo ----
#pragma unroll
        for (int it = 0; it < 8; it++) {
            int chunk = it * 128 + tid;       // 1024 chunks of 8 elems
            int r  = chunk >> 3;
            int kc = (chunk & 7) * 8;
            int row = row0 + r;
            float v[8];
            if (row < nrows) {
                const float4* p = (const float4*)(A + (size_t)row * KTOT + kt + kc);
                float4 a = p[0], b = p[1];
                v[0] = a.x; v[1] = a.y; v[2] = a.z; v[3] = a.w;
                v[4] = b.x; v[5] = b.y; v[6] = b.z; v[7] = b.w;
            } else {
#pragma unroll
                for (int j = 0; j < 8; j++) v[j] = 0.0f;
            }
#pragma unroll
            for (int j = 0; j < 4; j++) {
                __nv_bfloat162 h, l;
                h.x = __float2bfloat16(v[2 * j]);
                h.y = __float2bfloat16(v[2 * j + 1]);
                l.x = __float2bfloat16(v[2 * j]     - __bfloat162float(h.x));
                l.y = __float2bfloat16(v[2 * j + 1] - __bfloat162float(h.y));
                *(__nv_bfloat162*)&Ahi[r * APAD + kc + 2 * j] = h;
                *(__nv_bfloat162*)&Alo[r * APAD + kc + 2 * j] = l;
            }
        }
        // ---- B tile: Bs[n][k] = W[kt+k][n], 64x64 ----
#pragma unroll
        for (int it = 0; it < 32; it++) {
            int idx = it * 128 + tid;         // coalesced in n
            int n = idx & 63, k = idx >> 6;
            float w = W[(size_t)(kt + k) * HH + n];
            __nv_bfloat16 h = __float2bfloat16(w);
            Bhi[n * APAD + k] = h;
            Blo[n * APAD + k] = __float2bfloat16(w - __bfloat162float(h));
        }
        __syncthreads();

#pragma unroll
        for (int kc = 0; kc < 64; kc += 16) {
            uint32_t ah[2][4], al[2][4];
#pragma unroll
            for (int mt = 0; mt < 2; mt++) {
                int r = m0 + mt * 16 + g;
                ah[mt][0] = *(const uint32_t*)&Ahi[r * APAD + kc + tg * 2];
                ah[mt][1] = *(const uint32_t*)&Ahi[(r + 8) * APAD + kc + tg * 2];
                ah[mt][2] = *(const uint32_t*)&Ahi[r * APAD + kc + 8 + tg * 2];
                ah[mt][3] = *(const uint32_t*)&Ahi[(r + 8) * APAD + kc + 8 + tg * 2];
                al[mt][0] = *(const uint32_t*)&Alo[r * APAD + kc + tg * 2];
                al[mt][1] = *(const uint32_t*)&Alo[(r + 8) * APAD + kc + tg * 2];
                al[mt][2] = *(const uint32_t*)&Alo[r * APAD + kc + 8 + tg * 2];
                al[mt][3] = *(const uint32_t*)&Alo[(r + 8) * APAD + kc + 8 + tg * 2];
            }
#pragma unroll
            for (int nt = 0; nt < 8; nt++) {
                int n = nt * 8 + g;
                uint32_t bh0 = *(const uint32_t*)&Bhi[n * APAD + kc + tg * 2];
                uint32_t bh1 = *(const uint32_t*)&Bhi[n * APAD + kc + 8 + tg * 2];
                uint32_t bl0 = *(const uint32_t*)&Blo[n * APAD + kc + tg * 2];
                uint32_t bl1 = *(const uint32_t*)&Blo[n * APAD + kc + 8 + tg * 2];
#pragma unroll
                for (int mt = 0; mt < 2; mt++) {
                    mma_bf16(acc[mt][nt], ah[mt], bh0, bh1);   // hi*hi
                    mma_bf16(acc[mt][nt], ah[mt], bl0, bl1);   // hi*lo
                    mma_bf16(acc[mt][nt], al[mt], bh0, bh1);   // lo*hi
                }
            }
        }
        __syncthreads();
    }
}

// plain GEMM, fp16 output (feeds aggregation). NOTE: no minBlocks bound -> no spills.
template <int KTOT>
__global__ void __launch_bounds__(128)
gemm_tc(const float* __restrict__ A, const float* __restrict__ W,
        __half2* __restrict__ out, int nrows) {
    extern __shared__ char dsm[];
    const int tid = threadIdx.x, wid = tid >> 5, lane = tid & 31;
    const int g = lane >> 2, tg = lane & 3;
    const int row0 = blockIdx.x * 128;

    float acc[2][8][4];
#pragma unroll
    for (int mt = 0; mt < 2; mt++)
#pragma unroll
        for (int nt = 0; nt < 8; nt++)
#pragma unroll
            for (int j = 0; j < 4; j++) acc[mt][nt][j] = 0.0f;

    gemm_mainloop<KTOT>(A, W, nrows, dsm, row0, tid, wid, lane, g, tg, acc);

#pragma unroll
    for (int mt = 0; mt < 2; mt++) {
        int r0 = row0 + wid * 32 + mt * 16 + g;
        int r1 = r0 + 8;
#pragma unroll
        for (int nt = 0; nt < 8; nt++) {
            int h2c = nt * 4 + tg;            // half2 column
            if (r0 < nrows)
                out[(size_t)r0 * 32 + h2c] = __floats2half2_rn(acc[mt][nt][0], acc[mt][nt][1]);
            if (r1 < nrows)
                out[(size_t)r1 * 32 + h2c] = __floats2half2_rn(acc[mt][nt][2], acc[mt][nt][3]);
        }
    }
}

// GEMM (K=64) + bias/relu + fused MLP head (logits @ Wm2 + bm2, softmax)
__global__ void __launch_bounds__(128)
gemm_head(const float* __restrict__ A, const float* __restrict__ Wm1,
          const float* __restrict__ bm1, const float* __restrict__ Wm2,
          const float* __restrict__ bm2, float* __restrict__ out, int nrows) {
    extern __shared__ char dsm[];
    const int tid = threadIdx.x, wid = tid >> 5, lane = tid & 31;
    const int g = lane >> 2, tg = lane & 3;
    const int row0 = blockIdx.x * 128;

    float acc[2][8][4];
#pragma unroll
    for (int mt = 0; mt < 2; mt++)
#pragma unroll
        for (int nt = 0; nt < 8; nt++)
#pragma unroll
            for (int j = 0; j < 4; j++) acc[mt][nt][j] = 0.0f;

    gemm_mainloop<HH>(A, Wm1, nrows, dsm, row0, tid, wid, lane, g, tg, acc);

    // stage relu(acc + bm1) into smem [128][65] (reuses dead tile memory)
    float* st  = (float*)dsm;                 // 128*65*4 = 33280 B
    float* sW  = st + 128 * 65;               // 64*16*4  = 4096 B
    float* sbv = sW + 64 * 16;                // 16*4 B    (total 37440 < 55296)
#pragma unroll
    for (int mt = 0; mt < 2; mt++) {
        int rl0 = wid * 32 + mt * 16 + g;
#pragma unroll
        for (int nt = 0; nt < 8; nt++) {
            int c = nt * 8 + tg * 2;
            float b0 = __ldg(&bm1[c]), b1 = __ldg(&bm1[c + 1]);
            st[rl0 * 65 + c]           = fmaxf(acc[mt][nt][0] + b0, 0.0f);
            st[rl0 * 65 + c + 1]       = fmaxf(acc[mt][nt][1] + b1, 0.0f);
            st[(rl0 + 8) * 65 + c]     = fmaxf(acc[mt][nt][2] + b0, 0.0f);
            st[(rl0 + 8) * 65 + c + 1] = fmaxf(acc[mt][nt][3] + b1, 0.0f);
        }
    }
    for (int i = tid; i < HH * CC; i += 128) sW[i] = Wm2[i];
    if (tid < CC) sbv[tid] = bm2[tid];
    __syncthreads();

    int r = row0 + tid;                       // one row per thread
    if (r < nrows) {
        float lg[CC];
#pragma unroll
        for (int c = 0; c < CC; c++) lg[c] = sbv[c];
        const float* mrow = st + tid * 65;    // stride 65 -> conflict-free
#pragma unroll
        for (int k = 0; k < HH; k++) {
            float av = mrow[k];
#pragma unroll
            for (int c = 0; c < CC; c++) lg[c] += av * sW[k * CC + c];
        }
        float mx = lg[0];
#pragma unroll
        for (int c = 1; c < CC; c++) mx = fmaxf(mx, lg[c]);
        float ssum = 0.0f;
#pragma unroll
        for (int c = 0; c < CC; c++) { lg[c] = __expf(lg[c] - mx); ssum += lg[c]; }
        float inv = 1.0f / ssum;
        float4* op = (float4*)(out + (size_t)r * CC);
#pragma unroll
        for (int c4 = 0; c4 < 4; c4++)
            op[c4] = make_float4(lg[c4 * 4] * inv, lg[c4 * 4 + 1] * inv,
                                 lg[c4 * 4 + 2] * inv, lg[c4 * 4 + 3] * inv);
    }
}

// ---- edge aggregation: HALF-WARP per node (16 lanes x 8B = 128B/row) ----
// out[i] = relu( dinv[i] * ( dinv[i]*h[i] + sum_e val'[e]*h[col[e]] ) + bias )
__global__ void k_agg16(const uint2* __restrict__ hp, const float* __restrict__ bias,
                        float* __restrict__ out) {
    int gt = blockIdx.x * blockDim.x + threadIdx.x;
    int w  = gt >> 4;                          // node = half-warp
    int l  = gt & 15;                          // lane in half-warp, 4 feats each
    if (w >= NN) return;
    float di = g_dinv[w];

    uint2 hv = hp[(size_t)w * 16 + l];
    float2 h0 = __half22float2(*(const __half2*)&hv.x);
    float2 h1 = __half22float2(*(const __half2*)&hv.y);
    float a0 = di * h0.x, a1 = di * h0.y, a2 = di * h1.x, a3 = di * h1.y;

    int e  = __ldg(&g_rowptr[w]);
    int e1 = __ldg(&g_rowptr[w + 1]);
    for (; e + 2 <= e1; e += 2) {
        uint2 ev0 = g_edge[e], ev1 = g_edge[e + 1];
        uint2 p0 = hp[(size_t)ev0.x * 16 + l];
        uint2 p1 = hp[(size_t)ev1.x * 16 + l];
        float v0 = __uint_as_float(ev0.y), v1 = __uint_as_float(ev1.y);
        float2 q0 = __half22float2(*(const __half2*)&p0.x);
        float2 q1 = __half22float2(*(const __half2*)&p0.y);
        float2 r0 = __half22float2(*(const __half2*)&p1.x);
        float2 r1 = __half22float2(*(const __half2*)&p1.y);
        a0 += v0 * q0.x; a1 += v0 * q0.y; a2 += v0 * q1.x; a3 += v0 * q1.y;
        a0 += v1 * r0.x; a1 += v1 * r0.y; a2 += v1 * r1.x; a3 += v1 * r1.y;
    }
    if (e < e1) {
        uint2 ev = g_edge[e];
        uint2 p  = hp[(size_t)ev.x * 16 + l];
        float v  = __uint_as_float(ev.y);
        float2 q0 = __half22float2(*(const __half2*)&p.x);
        float2 q1 = __half22float2(*(const __half2*)&p.y);
        a0 += v * q0.x; a1 += v * q0.y; a2 += v * q1.x; a3 += v * q1.y;
    }
    float4 bv = *(const float4*)&bias[4 * l];
    *(float4*)&out[(size_t)w * HH + 4 * l] =
        make_float4(fmaxf(di * a0 + bv.x, 0.0f), fmaxf(di * a1 + bv.y, 0.0f),
                    fmaxf(di * a2 + bv.z, 0.0f), fmaxf(di * a3 + bv.w, 0.0f));
}

// ---------------- launch ----------------
extern "C" void kernel_launch(void* const* d_in, const int* in_sizes, int n_in,
                              void* d_out, int out_size) {
    const float* x   = (const float*)d_in[0];
    const void*  ei  = d_in[1];
    const float* ew  = (const float*)d_in[2];
    const float* W1  = (const float*)d_in[3];
    const float* b1  = (const float*)d_in[4];
    const float* W2  = (const float*)d_in[5];
    const float* b2  = (const float*)d_in[6];
    const float* Wm1 = (const float*)d_in[7];
    const float* bm1 = (const float*)d_in[8];
    const float* Wm2 = (const float*)d_in[9];
    const float* bm2 = (const float*)d_in[10];
    float* out = (float*)d_out;

    float *pA, *pB, *pDeg;
    int *pCnt, *pArr;
    cudaGetSymbolAddress((void**)&pA,   g_bufA);
    cudaGetSymbolAddress((void**)&pB,   g_bufB);
    cudaGetSymbolAddress((void**)&pDeg, g_deg);
    cudaGetSymbolAddress((void**)&pCnt, g_cnt);
    cudaGetSymbolAddress((void**)&pArr, g_arrive);
    __half2* pA16 = (__half2*)pA;

    static cudaStream_t s2 = 0;
    static cudaEvent_t evA = 0, evB = 0;
    if (!s2) {
        cudaStreamCreateWithFlags(&s2, cudaStreamNonBlocking);
        cudaEventCreateWithFlags(&evA, cudaEventDisableTiming);
        cudaEventCreateWithFlags(&evB, cudaEventDisableTiming);
        cudaFuncSetAttribute(gemm_tc<INF>, cudaFuncAttributeMaxDynamicSharedMemorySize, SMEM_DYN);
        cudaFuncSetAttribute(gemm_tc<HH>,  cudaFuncAttributeMaxDynamicSharedMemorySize, SMEM_DYN);
        cudaFuncSetAttribute(gemm_head,    cudaFuncAttributeMaxDynamicSharedMemorySize, SMEM_DYN);
    }

    const int gemm_grid = (NN + 127) / 128;
    const int agg_grid  = (NN * 16 + 255) / 256;
    const int nblk      = (NN + 1023) / 1024;        // 98

    // fork: GEMM1 (x @ W1 -> fp16 h) runs alongside CSR build
    cudaEventRecord(evA, 0);
    cudaStreamWaitEvent(s2, evA, 0);
    gemm_tc<INF><<<gemm_grid, 128, SMEM_DYN, s2>>>(x, W1, pA16, NN);
    cudaEventRecord(evB, s2);

    // CSR build on main stream (memset nodes replace init kernel)
    cudaMemsetAsync(pDeg, 0, NN * sizeof(float), 0);
    cudaMemsetAsync(pCnt, 0, NN * sizeof(int), 0);
    cudaMemsetAsync(pArr, 0, sizeof(int), 0);
    k_detect<<<1, 32>>>((const unsigned int*)ei);
    k_degcnt<<<(EE + 255) / 256, 256>>>(ei, ew);
    k_scanA<<<nblk, 1024>>>();
    k_scanC<<<(NN + 255) / 256, 256>>>();
    k_scatter<<<(EE + 255) / 256, 256>>>(ei, ew);

    cudaStreamWaitEvent(0, evB, 0);                  // join GEMM1

    k_agg16<<<agg_grid, 256>>>((const uint2*)pA16, b1, pB);           // conv1+relu
    gemm_tc<HH><<<gemm_grid, 128, SMEM_DYN>>>(pB, W2, pA16, NN);      // h2 (fp16)
    k_agg16<<<agg_grid, 256>>>((const uint2*)pA16, b2, pB);           // conv2+relu
    gemm_head<<<gemm_grid, 128, SMEM_DYN>>>(pB, Wm1, bm1, Wm2, bm2, out, NN);
}

// round 9
// speedup vs baseline: 2.4786x; 1.0786x over previous
#include <cuda_runtime.h>
#include <cuda_bf16.h>
#include <cuda_fp16.h>
#include <cstdint>

#define NN  100000
#define EE  1600000
#define INF 256
#define HH  64
#define CC  16

// ---------------- scratch (no allocations allowed -> device globals) ----------------
__device__ float g_bufA[(size_t)NN * HH];   // holds fp16 h (12.8 MB)
__device__ float g_bufB[(size_t)NN * HH];   // holds fp16 h (12.8 MB)
__device__ float g_deg[NN];                 // weighted in-degree (excl. self loop)
__device__ float g_dinv[NN];
__device__ int   g_cnt[NN];
__device__ int   g_rowptr[NN + 1];
__device__ int   g_rank[EE];                // rank of edge within its dst bucket
__device__ uint2 g_edge[EE];                // packed (src, val) 8B
__device__ int   g_idx64;
__device__ int   g_blksum[128];
__device__ int   g_blkoff[128];
__device__ int   g_arrive;

// edge_index may be int64 (reference declares it) or int32 (jax x64-disabled
// canonicalization). Detected at runtime; branch on device flag.
__device__ __forceinline__ int ld_idx(const void* ei, long long pos) {
    if (g_idx64)
        return (int)((const long long*)ei)[pos];
    return ((const int*)ei)[pos];
}

// odd 32-bit words of the first 64 entries all zero iff int64 (indices < 1e5).
__global__ void k_detect(const unsigned int* ei) {
    if (threadIdx.x == 0) {
        unsigned v = 0;
        for (int j = 0; j < 64; j++) v |= ei[2 * j + 1];
        g_idx64 = (v == 0) ? 1 : 0;
    }
}

// pass 1 over edges: weighted degree (no-return reduce) + count (return = rank)
__global__ void k_degcnt(const void* ei, const float* __restrict__ ew) {
    int e = blockIdx.x * blockDim.x + threadIdx.x;
    if (e < EE) {
        int d = ld_idx(ei, (long long)EE + e);       // dst row
        atomicAdd(&g_deg[d], ew[e]);                 // result unused -> RED
        g_rank[e] = atomicAdd(&g_cnt[d], 1);
    }
}

// ---- scan phase A: shuffle block scan; ticketed last block scans block sums ----
__global__ void k_scanA() {
    __shared__ int wsum[32];
    __shared__ int sb[128];
    __shared__ int s_last;
    const int t    = threadIdx.x;
    const int lane = t & 31;
    const int warp = t >> 5;
    int i = blockIdx.x * 1024 + t;
    int v = (i < NN) ? g_cnt[i] : 0;

    int x = v;
#pragma unroll
    for (int off = 1; off < 32; off <<= 1) {
        int y = __shfl_up_sync(0xffffffff, x, off);
        if (lane >= off) x += y;
    }
    if (lane == 31) wsum[warp] = x;
    __syncthreads();
    if (warp == 0) {
        int w = (lane < 32) ? wsum[lane] : 0;
#pragma unroll
        for (int off = 1; off < 32; off <<= 1) {
            int y = __shfl_up_sync(0xffffffff, w, off);
            if (lane >= off) w += y;
        }
        wsum[lane] = w;                              // inclusive warp sums
    }
    __syncthreads();
    int incl = x + (warp ? wsum[warp - 1] : 0);
    if (i < NN) g_rowptr[i] = incl - v;              // block-local exclusive
    if (t == 1023) g_blksum[blockIdx.x] = incl;
    __threadfence();
    __syncthreads();
    if (t == 0) s_last = (atomicAdd(&g_arrive, 1) == (int)gridDim.x - 1);
    __syncthreads();
    if (s_last) {                                    // uniform branch
        int nb = (int)gridDim.x;
        int bv = (t < 128 && t < nb) ? g_blksum[t] : 0;
        if (t < 128) sb[t] = bv;
        __syncthreads();
        for (int off = 1; off < 128; off <<= 1) {
            int a = (t < 128 && t >= off) ? sb[t - off] : 0;
            __syncthreads();
            if (t < 128) sb[t] += a;
            __syncthreads();
        }
        if (t < nb) g_blkoff[t] = sb[t] - bv;        // exclusive
    }
}

__global__ void k_scanC() {
    int i = blockIdx.x * blockDim.x + threadIdx.x;
    if (i < NN) {
        g_rowptr[i] = g_rowptr[i] + g_blkoff[i >> 10];
        g_dinv[i]   = rsqrtf(1.0f + g_deg[i]);       // +1 = self-loop weight
    }
    if (i == 0) g_rowptr[NN] = EE;
}

// pass 2 over edges: atomic-free placement via rowptr + rank, packed 8B store.
// stored val = dinv[src]*w  (dinv[dst] applied once per node in agg)
__global__ void k_scatter(const void* ei, const float* __restrict__ ew) {
    int e = blockIdx.x * blockDim.x + threadIdx.x;
    if (e < EE) {
        int s = ld_idx(ei, e);
        int d = ld_idx(ei, (long long)EE + e);
        int pos = g_rowptr[d] + g_rank[e];
        float v = g_dinv[s] * ew[e];
        g_edge[pos] = make_uint2((unsigned)s, __float_as_uint(v));
    }
}

// ================================ GEMM kernels ================================
#define APAD 72                               // 16-bit row stride (conflict-free frags)

// ---- GEMM1: fp32 A, bf16 hi/lo split (3 MMAs), fp16 out ----
#define SM_AHI 0
#define SM_ALO (128 * APAD)
#define SM_BHI (2 * 128 * APAD)
#define SM_BLO (2 * 128 * APAD + 64 * APAD)
#define SMEM_DYN ((2 * 128 * APAD + 2 * 64 * APAD) * 2)   // 55296 B

// ---- GEMM2/head: fp16 A exact (2 MMAs), W hi/lo split ----
#define SMF_A   0
#define SMF_BHI (128 * APAD)
#define SMF_BLO (128 * APAD + 64 * APAD)
#define SMEM_F16 ((128 * APAD + 2 * 64 * APAD) * 2)        // 36864 B
#define SMEM_HEAD 37504                                    // head stage needs 37440

__device__ __forceinline__ void mma_bf16(float* c, const uint32_t* a,
                                         uint32_t b0, uint32_t b1) {
    asm volatile(
        "mma.sync.aligned.m16n8k16.row.col.f32.bf16.bf16.f32 "
        "{%0,%1,%2,%3}, {%4,%5,%6,%7}, {%8,%9}, {%0,%1,%2,%3};"
        : "+f"(c[0]), "+f"(c[1]), "+f"(c[2]), "+f"(c[3])
        : "r"(a[0]), "r"(a[1]), "r"(a[2]), "r"(a[3]), "r"(b0), "r"(b1));
}
__device__ __forceinline__ void mma_f16(float* c, const uint32_t* a,
                                        uint32_t b0, uint32_t b1) {
    asm volatile(
        "mma.sync.aligned.m16n8k16.row.col.f32.f16.f16.f32 "
        "{%0,%1,%2,%3}, {%4,%5,%6,%7}, {%8,%9}, {%0,%1,%2,%3};"
        : "+f"(c[0]), "+f"(c[1]), "+f"(c[2]), "+f"(c[3])
        : "r"(a[0]), "r"(a[1]), "r"(a[2]), "r"(a[3]), "r"(b0), "r"(b1));
}

// bf16-split mainloop (GEMM1), fp32 A
template <int KTOT>
__device__ __forceinline__ void gemm_mainloop_bf16(
    const float* __restrict__ A, const float* __restrict__ W, int nrows,
    char* dsm, int row0, int tid, int wid, int g, int tg, float acc[2][8][4]) {
    __nv_bfloat16* Ahi = (__nv_bfloat16*)dsm + SM_AHI;
    __nv_bfloat16* Alo = (__nv_bfloat16*)dsm + SM_ALO;
    __nv_bfloat16* Bhi = (__nv_bfloat16*)dsm + SM_BHI;
    __nv_bfloat16* Blo = (__nv_bfloat16*)dsm + SM_BLO;
    const int m0 = wid * 32;

    for (int kt = 0; kt < KTOT; kt += 64) {
#pragma unroll
        for (int it = 0; it < 8; it++) {
            int chunk = it * 128 + tid;
            int r  = chunk >> 3;
            int kc = (chunk & 7) * 8;
            int row = row0 + r;
            float v[8];
            if (row < nrows) {
                const float4* p = (const float4*)(A + (size_t)row * KTOT + kt + kc);
                float4 a = p[0], b = p[1];
                v[0] = a.x; v[1] = a.y; v[2] = a.z; v[3] = a.w;
                v[4] = b.x; v[5] = b.y; v[6] = b.z; v[7] = b.w;
            } else {
#pragma unroll
                for (int j = 0; j < 8; j++) v[j] = 0.0f;
            }
#pragma unroll
            for (int j = 0; j < 4; j++) {
                __nv_bfloat162 h, l;
                h.x = __float2bfloat16(v[2 * j]);
                h.y = __float2bfloat16(v[2 * j + 1]);
                l.x = __float2bfloat16(v[2 * j]     - __bfloat162float(h.x));
                l.y = __float2bfloat16(v[2 * j + 1] - __bfloat162float(h.y));
                *(__nv_bfloat162*)&Ahi[r * APAD + kc + 2 * j] = h;
                *(__nv_bfloat162*)&Alo[r * APAD + kc + 2 * j] = l;
            }
        }
#pragma unroll
        for (int it = 0; it < 32; it++) {
            int idx = it * 128 + tid;
            int n = idx & 63, k = idx >> 6;
            float w = W[(size_t)(kt + k) * HH + n];
            __nv_bfloat16 h = __float2bfloat16(w);
            Bhi[n * APAD + k] = h;
            Blo[n * APAD + k] = __float2bfloat16(w - __bfloat162float(h));
        }
        __syncthreads();

#pragma unroll
        for (int kc = 0; kc < 64; kc += 16) {
            uint32_t ah[2][4], al[2][4];
#pragma unroll
            for (int mt = 0; mt < 2; mt++) {
                int r = m0 + mt * 16 + g;
                ah[mt][0] = *(const uint32_t*)&Ahi[r * APAD + kc + tg * 2];
                ah[mt][1] = *(const uint32_t*)&Ahi[(r + 8) * APAD + kc + tg * 2];
                ah[mt][2] = *(const uint32_t*)&Ahi[r * APAD + kc + 8 + tg * 2];
                ah[mt][3] = *(const uint32_t*)&Ahi[(r + 8) * APAD + kc + 8 + tg * 2];
                al[mt][0] = *(const uint32_t*)&Alo[r * APAD + kc + tg * 2];
                al[mt][1] = *(const uint32_t*)&Alo[(r + 8) * APAD + kc + tg * 2];
                al[mt][2] = *(const uint32_t*)&Alo[r * APAD + kc + 8 + tg * 2];
                al[mt][3] = *(const uint32_t*)&Alo[(r + 8) * APAD + kc + 8 + tg * 2];
            }
#pragma unroll
            for (int nt = 0; nt < 8; nt++) {
                int n = nt * 8 + g;
                uint32_t bh0 = *(const uint32_t*)&Bhi[n * APAD + kc + tg * 2];
                uint32_t bh1 = *(const uint32_t*)&Bhi[n * APAD + kc + 8 + tg * 2];
                uint32_t bl0 = *(const uint32_t*)&Blo[n * APAD + kc + tg * 2];
                uint32_t bl1 = *(const uint32_t*)&Blo[n * APAD + kc + 8 + tg * 2];
#pragma unroll
                for (int mt = 0; mt < 2; mt++) {
                    mma_bf16(acc[mt][nt], ah[mt], bh0, bh1);   // hi*hi
                    mma_bf16(acc[mt][nt], ah[mt], bl0, bl1);   // hi*lo
                    mma_bf16(acc[mt][nt], al[mt], bh0, bh1);   // lo*hi
                }
            }
        }
        __syncthreads();
    }
}

// fp16-exact-A mainloop (K=64): A from fp16 table, W split hi/lo (2 MMAs)
__device__ __forceinline__ void gemm_mainloop_f16(
    const uint2* __restrict__ A16, const float* __restrict__ W, int nrows,
    char* dsm, int row0, int tid, int wid, int g, int tg, float acc[2][8][4]) {
    __half* Ah  = (__half*)dsm + SMF_A;
    __half* Bhi = (__half*)dsm + SMF_BHI;
    __half* Blo = (__half*)dsm + SMF_BLO;
    const int m0 = wid * 32;

#pragma unroll
    for (int it = 0; it < 16; it++) {                // A: 128 rows x 64 fp16
        int idx = it * 128 + tid;
        int r = idx >> 4, c = idx & 15;              // c = 8B chunk (4 halfs)
        int row = row0 + r;
        uint2 v = (row < nrows) ? A16[(size_t)row * 16 + c] : make_uint2(0u, 0u);
        *(uint2*)&Ah[r * APAD + c * 4] = v;
    }
#pragma unroll
    for (int it = 0; it < 32; it++) {                // B: W[k][n] -> Bs[n][k]
        int idx = it * 128 + tid;
        int n = idx & 63, k = idx >> 6;
        float w = W[(size_t)k * HH + n];
        __half h = __float2half_rn(w);
        Bhi[n * APAD + k] = h;
        Blo[n * APAD + k] = __float2half_rn(w - __half2float(h));
    }
    __syncthreads();

#pragma unroll
    for (int kc = 0; kc < 64; kc += 16) {
        uint32_t a[2][4];
#pragma unroll
        for (int mt = 0; mt < 2; mt++) {
            int r = m0 + mt * 16 + g;
            a[mt][0] = *(const uint32_t*)&Ah[r * APAD + kc + tg * 2];
            a[mt][1] = *(const uint32_t*)&Ah[(r + 8) * APAD + kc + tg * 2];
            a[mt][2] = *(const uint32_t*)&Ah[r * APAD + kc + 8 + tg * 2];
            a[mt][3] = *(const uint32_t*)&Ah[(r + 8) * APAD + kc + 8 + tg * 2];
        }
#pragma unroll
        for (int nt = 0; nt < 8; nt++) {
            int n = nt * 8 + g;
            uint32_t bh0 = *(const uint32_t*)&Bhi[n * APAD + kc + tg * 2];
            uint32_t bh1 = *(const uint32_t*)&Bhi[n * APAD + kc + 8 + tg * 2];
            uint32_t bl0 = *(const uint32_t*)&Blo[n * APAD + kc + tg * 2];
            uint32_t bl1 = *(const uint32_t*)&Blo[n * APAD + kc + 8 + tg * 2];
#pragma unroll
            for (int mt = 0; mt < 2; mt++) {
                mma_f16(acc[mt][nt], a[mt], bh0, bh1);   // A*Whi
                mma_f16(acc[mt][nt], a[mt], bl0, bl1);   // A*Wlo
            }
        }
    }
    __syncthreads();                                 // smem reusable after this
}

// fp16 epilogue writer (h layout: row * 32 half2, feature-linear)
__device__ __forceinline__ void write_h16(__half2* out, int nrows, int row0,
                                          int wid, int g, int tg, float acc[2][8][4]) {
#pragma unroll
    for (int mt = 0; mt < 2; mt++) {
        int r0 = row0 + wid * 32 + mt * 16 + g;
        int r1 = r0 + 8;
#pragma unroll
        for (int nt = 0; nt < 8; nt++) {
            int h2c = nt * 4 + tg;
            if (r0 < nrows)
                out[(size_t)r0 * 32 + h2c] = __floats2half2_rn(acc[mt][nt][0], acc[mt][nt][1]);
            if (r1 < nrows)
                out[(size_t)r1 * 32 + h2c] = __floats2half2_rn(acc[mt][nt][2], acc[mt][nt][3]);
        }
    }
}

// GEMM1: x(fp32) @ W1 -> fp16 h
template <int KTOT>
__global__ void __launch_bounds__(128)
gemm_tc(const float* __restrict__ A, const float* __restrict__ W,
        __half2* __restrict__ out, int nrows) {
    extern __shared__ char dsm[];
    const int tid = threadIdx.x, wid = tid >> 5, lane = tid & 31;
    const int g = lane >> 2, tg = lane & 3;
    const int row0 = blockIdx.x * 128;
    float acc[2][8][4];
#pragma unroll
    for (int mt = 0; mt < 2; mt++)
#pragma unroll
        for (int nt = 0; nt < 8; nt++)
#pragma unroll
            for (int j = 0; j < 4; j++) acc[mt][nt][j] = 0.0f;
    gemm_mainloop_bf16<KTOT>(A, W, nrows, dsm, row0, tid, wid, g, tg, acc);
    write_h16(out, nrows, row0, wid, g, tg, acc);
}

// GEMM2: h(fp16) @ W2 -> fp16 h
__global__ void __launch_bounds__(128)
gemm_f16(const uint2* __restrict__ A16, const float* __restrict__ W,
         __half2* __restrict__ out, int nrows) {
    extern __shared__ char dsm[];
    const int tid = threadIdx.x, wid = tid >> 5, lane = tid & 31;
    const int g = lane >> 2, tg = lane & 3;
    const int row0 = blockIdx.x * 128;
    float acc[2][8][4];
#pragma unroll
    for (int mt = 0; mt < 2; mt++)
#pragma unroll
        for (int nt = 0; nt < 8; nt++)
#pragma unroll
            for (int j = 0; j < 4; j++) acc[mt][nt][j] = 0.0f;
    gemm_mainloop_f16(A16, W, nrows, dsm, row0, tid, wid, g, tg, acc);
    write_h16(out, nrows, row0, wid, g, tg, acc);
}

// GEMM3 (fp16 A) + bias/relu + fused MLP head (logits @ Wm2 + bm2, softmax)
__global__ void __launch_bounds__(128)
gemm_head(const uint2* __restrict__ A16, const float* __restrict__ Wm1,
          const float* __restrict__ bm1, const float* __restrict__ Wm2,
          const float* __restrict__ bm2, float* __restrict__ out, int nrows) {
    extern __shared__ char dsm[];
    const int tid = threadIdx.x, wid = tid >> 5, lane = tid & 31;
    const int g = lane >> 2, tg = lane & 3;
    const int row0 = blockIdx.x * 128;
    float acc[2][8][4];
#pragma unroll
    for (int mt = 0; mt < 2; mt++)
#pragma unroll
        for (int nt = 0; nt < 8; nt++)
#pragma unroll
            for (int j = 0; j < 4; j++) acc[mt][nt][j] = 0.0f;
    gemm_mainloop_f16(A16, Wm1, nrows, dsm, row0, tid, wid, g, tg, acc);

    // stage relu(acc + bm1) into smem [128][65] (tile memory dead after mainloop)
    float* st  = (float*)dsm;                 // 33280 B
    float* sW  = st + 128 * 65;               // 4096 B
    float* sbv = sW + 64 * 16;                // 64 B  (total 37440 <= SMEM_HEAD)
#pragma unroll
    for (int mt = 0; mt < 2; mt++) {
        int rl0 = wid * 32 + mt * 16 + g;
#pragma unroll
        for (int nt = 0; nt < 8; nt++) {
            int c = nt * 8 + tg * 2;
            float b0 = __ldg(&bm1[c]), b1 = __ldg(&bm1[c + 1]);
            st[rl0 * 65 + c]           = fmaxf(acc[mt][nt][0] + b0, 0.0f);
            st[rl0 * 65 + c + 1]       = fmaxf(acc[mt][nt][1] + b1, 0.0f);
            st[(rl0 + 8) * 65 + c]     = fmaxf(acc[mt][nt][2] + b0, 0.0f);
            st[(rl0 + 8) * 65 + c + 1] = fmaxf(acc[mt][nt][3] + b1, 0.0f);
        }
    }
    for (int i = tid; i < HH * CC; i += 128) sW[i] = Wm2[i];
    if (tid < CC) sbv[tid] = bm2[tid];
    __syncthreads();

    int r = row0 + tid;                       // one row per thread
    if (r < nrows) {
        float lg[CC];
#pragma unroll
        for (int c = 0; c < CC; c++) lg[c] = sbv[c];
        const float* mrow = st + tid * 65;    // stride 65 -> conflict-free
#pragma unroll
        for (int k = 0; k < HH; k++) {
            float av = mrow[k];
#pragma unroll
            for (int c = 0; c < CC; c++) lg[c] += av * sW[k * CC + c];
        }
        float mx = lg[0];
#pragma unroll
        for (int c = 1; c < CC; c++) mx = fmaxf(mx, lg[c]);
        float ssum = 0.0f;
#pragma unroll
        for (int c = 0; c < CC; c++) { lg[c] = __expf(lg[c] - mx); ssum += lg[c]; }
        float inv = 1.0f / ssum;
        float4* op = (float4*)(out + (size_t)r * CC);
#pragma unroll
        for (int c4 = 0; c4 < 4; c4++)
            op[c4] = make_float4(lg[c4 * 4] * inv, lg[c4 * 4 + 1] * inv,
                                 lg[c4 * 4 + 2] * inv, lg[c4 * 4 + 3] * inv);
    }
}

// ---- edge aggregation: HALF-WARP per node, 4x unrolled, fp16 in/out ----
// out[i] = relu( dinv[i] * ( dinv[i]*h[i] + sum_e val'[e]*h[col[e]] ) + bias )
__global__ void k_agg16(const uint2* __restrict__ hp, const float* __restrict__ bias,
                        uint2* __restrict__ out) {
    int gt = blockIdx.x * blockDim.x + threadIdx.x;
    int w  = gt >> 4;                          // node = half-warp
    int l  = gt & 15;                          // lane: feats 4l..4l+3
    if (w >= NN) return;
    float di = g_dinv[w];

    uint2 hv = hp[(size_t)w * 16 + l];
    float2 h0 = __half22float2(*(const __half2*)&hv.x);
    float2 h1 = __half22float2(*(const __half2*)&hv.y);
    float a0 = di * h0.x, a1 = di * h0.y, a2 = di * h1.x, a3 = di * h1.y;

    int e  = __ldg(&g_rowptr[w]);
    int e1 = __ldg(&g_rowptr[w + 1]);
    for (; e + 4 <= e1; e += 4) {
        uint2 ev0 = g_edge[e],     ev1 = g_edge[e + 1];
        uint2 ev2 = g_edge[e + 2], ev3 = g_edge[e + 3];
        uint2 p0 = hp[(size_t)ev0.x * 16 + l];
        uint2 p1 = hp[(size_t)ev1.x * 16 + l];
        uint2 p2 = hp[(size_t)ev2.x * 16 + l];
        uint2 p3 = hp[(size_t)ev3.x * 16 + l];
        float v0 = __uint_as_float(ev0.y), v1 = __uint_as_float(ev1.y);
        float v2 = __uint_as_float(ev2.y), v3 = __uint_as_float(ev3.y);
        float2 q;
        q = __half22float2(*(const __half2*)&p0.x); a0 += v0 * q.x; a1 += v0 * q.y;
        q = __half22float2(*(const __half2*)&p0.y); a2 += v0 * q.x; a3 += v0 * q.y;
        q = __half22float2(*(const __half2*)&p1.x); a0 += v1 * q.x; a1 += v1 * q.y;
        q = __half22float2(*(const __half2*)&p1.y); a2 += v1 * q.x; a3 += v1 * q.y;
        q = __half22float2(*(const __half2*)&p2.x); a0 += v2 * q.x; a1 += v2 * q.y;
        q = __half22float2(*(const __half2*)&p2.y); a2 += v2 * q.x; a3 += v2 * q.y;
        q = __half22float2(*(const __half2*)&p3.x); a0 += v3 * q.x; a1 += v3 * q.y;
        q = __half22float2(*(const __half2*)&p3.y); a2 += v3 * q.x; a3 += v3 * q.y;
    }
    for (; e < e1; e++) {
        uint2 ev = g_edge[e];
        uint2 p  = hp[(size_t)ev.x * 16 + l];
        float v  = __uint_as_float(ev.y);
        float2 q;
        q = __half22float2(*(const __half2*)&p.x); a0 += v * q.x; a1 += v * q.y;
        q = __half22float2(*(const __half2*)&p.y); a2 += v * q.x; a3 += v * q.y;
    }
    float4 bv = *(const float4*)&bias[4 * l];
    __half2 o0 = __floats2half2_rn(fmaxf(di * a0 + bv.x, 0.0f),
                                   fmaxf(di * a1 + bv.y, 0.0f));
    __half2 o1 = __floats2half2_rn(fmaxf(di * a2 + bv.z, 0.0f),
                                   fmaxf(di * a3 + bv.w, 0.0f));
    out[(size_t)w * 16 + l] = make_uint2(*(uint32_t*)&o0, *(uint32_t*)&o1);
}

// ---------------- launch ----------------
extern "C" void kernel_launch(void* const* d_in, const int* in_sizes, int n_in,
                              void* d_out, int out_size) {
    const float* x   = (const float*)d_in[0];
    const void*  ei  = d_in[1];
    const float* ew  = (const float*)d_in[2];
    const float* W1  = (const float*)d_in[3];
    const float* b1  = (const float*)d_in[4];
    const float* W2  = (const float*)d_in[5];
    const float* b2  = (const float*)d_in[6];
    const float* Wm1 = (const float*)d_in[7];
    const float* bm1 = (const float*)d_in[8];
    const float* Wm2 = (const float*)d_in[9];
    const float* bm2 = (const float*)d_in[10];
    float* out = (float*)d_out;

    float *pA, *pB, *pDeg;
    int *pCnt, *pArr;
    cudaGetSymbolAddress((void**)&pA,   g_bufA);
    cudaGetSymbolAddress((void**)&pB,   g_bufB);
    cudaGetSymbolAddress((void**)&pDeg, g_deg);
    cudaGetSymbolAddress((void**)&pCnt, g_cnt);
    cudaGetSymbolAddress((void**)&pArr, g_arrive);
    __half2* pA16 = (__half2*)pA;
    __half2* pB16 = (__half2*)pB;

    static cudaStream_t s2 = 0;
    static cudaEvent_t evA = 0, evB = 0;
    if (!s2) {
        cudaStreamCreateWithFlags(&s2, cudaStreamNonBlocking);
        cudaEventCreateWithFlags(&evA, cudaEventDisableTiming);
        cudaEventCreateWithFlags(&evB, cudaEventDisableTiming);
        cudaFuncSetAttribute(gemm_tc<INF>, cudaFuncAttributeMaxDynamicSharedMemorySize, SMEM_DYN);
        cudaFuncSetAttribute(gemm_f16,     cudaFuncAttributeMaxDynamicSharedMemorySize, SMEM_F16);
        cudaFuncSetAttribute(gemm_head,    cudaFuncAttributeMaxDynamicSharedMemorySize, SMEM_HEAD);
    }

    const int gemm_grid = (NN + 127) / 128;
    const int agg_grid  = (NN * 16 + 255) / 256;
    const int nblk      = (NN + 1023) / 1024;        // 98

    // fork: GEMM1 (x @ W1 -> fp16 h) alongside CSR build
    cudaEventRecord(evA, 0);
    cudaStreamWaitEvent(s2, evA, 0);
    gemm_tc<INF><<<gemm_grid, 128, SMEM_DYN, s2>>>(x, W1, pA16, NN);
    cudaEventRecord(evB, s2);

    // CSR build on main stream
    cudaMemsetAsync(pDeg, 0, NN * sizeof(float), 0);
    cudaMemsetAsync(pCnt, 0, NN * sizeof(int), 0);
    cudaMemsetAsync(pArr, 0, sizeof(int), 0);
    k_detect<<<1, 32>>>((const unsigned int*)ei);
    k_degcnt<<<(EE + 255) / 256, 256>>>(ei, ew);
    k_scanA<<<nblk, 1024>>>();
    k_scanC<<<(NN + 255) / 256, 256>>>();
    k_scatter<<<(EE + 255) / 256, 256>>>(ei, ew);

    cudaStreamWaitEvent(0, evB, 0);                  // join GEMM1

    k_agg16<<<agg_grid, 256>>>((const uint2*)pA16, b1, (uint2*)pB16);   // conv1+relu
    gemm_f16<<<gemm_grid, 128, SMEM_F16>>>((const uint2*)pB16, W2, pA16, NN);
    k_agg16<<<agg_grid, 256>>>((const uint2*)pA16, b2, (uint2*)pB16);   // conv2+relu
    gemm_head<<<gemm_grid, 128, SMEM_HEAD>>>((const uint2*)pB16, Wm1, bm1, Wm2, bm2, out, NN);
}